// round 8
// baseline (speedup 1.0000x reference)
#include <cuda_runtime.h>
#include <cuda_bf16.h>

typedef unsigned int       u32;
typedef unsigned long long u64;

// Problem constants
#define B_     4
#define N_     16384
#define KNN    16
#define CIN    64
#define CP     68
#define JTOT   1088           // j' = c*16 + w
#define NCHUNK 17             // 17 chunks of 64 j'
#define COUT   128
#define MT     128            // points per block
#define NEG_SLOPE 0.1f
#define WK_STRIDE 260

// smem byte offsets (A/W tiles 1024-aligned for the 128B swizzle)
#define A_HI_OFF   0                            // 128x64 bf16 = 16384 B
#define A_LO_OFF   16384
#define W_HI_OFF   32768
#define W_LO_OFF   49152
#define WK_OFF     65536                        // float[128][260] = 133120 B
#define GID_OFF    (WK_OFF + 133120)            // int[128*16] = 8192 B
#define SMEM_TOTAL (GID_OFF + 8192)             // 206848 B

#define STAGE_STRIDE 132                        // epilogue f32 stage stride

// Static device scratch
__device__ __align__(16) float          g_feats[B_ * N_ * CP];
__device__ __align__(16) __nv_bfloat16  g_w_hi[NCHUNK * 128 * 64];   // pre-swizzled tiles
__device__ __align__(16) __nv_bfloat16  g_w_lo[NCHUNK * 128 * 64];

__device__ __forceinline__ float leaky(float x) { return x >= 0.f ? x : NEG_SLOPE * x; }

// ---- helpers ----------------------------------------------------------------
__device__ __forceinline__ u32 s2u(const void* p) {
    u32 a;
    asm("{ .reg .u64 t; cvta.to.shared.u64 t, %1; cvt.u32.u64 %0, t; }" : "=r"(a) : "l"(p));
    return a;
}
__device__ __forceinline__ u64 fma2(u64 a, u64 b, u64 c) {
    u64 d; asm("fma.rn.f32x2 %0, %1, %2, %3;" : "=l"(d) : "l"(a), "l"(b), "l"(c)); return d;
}
__device__ __forceinline__ u64 pack2(float x, float y) {
    u64 d; asm("mov.b64 %0, {%1, %2};" : "=l"(d) : "f"(x), "f"(y)); return d;
}
__device__ __forceinline__ float2 unpack2(u64 v) {
    float2 r; asm("mov.b64 {%0, %1}, %2;" : "=f"(r.x), "=f"(r.y) : "l"(v)); return r;
}
__device__ __forceinline__ u32 sw128(u32 off) { return off ^ ((off >> 3) & 0x70); }

__device__ __forceinline__ void ldsm4(u32* r, u32 addr) {
    asm volatile("ldmatrix.sync.aligned.m8n8.x4.shared.b16 {%0,%1,%2,%3}, [%4];"
                 : "=r"(r[0]), "=r"(r[1]), "=r"(r[2]), "=r"(r[3]) : "r"(addr));
}
__device__ __forceinline__ void mma_bf16(float* c, const u32* a, u32 b0, u32 b1) {
    asm volatile("mma.sync.aligned.m16n8k16.row.col.f32.bf16.bf16.f32 "
                 "{%0,%1,%2,%3}, {%4,%5,%6,%7}, {%8,%9}, {%0,%1,%2,%3};"
                 : "+f"(c[0]), "+f"(c[1]), "+f"(c[2]), "+f"(c[3])
                 : "r"(a[0]), "r"(a[1]), "r"(a[2]), "r"(a[3]), "r"(b0), "r"(b1));
}

// ---------------------------------------------------------------------------
// pack_w: lin_w [128, 16*67] -> hi/lo bf16 tiles, j' = c*16+w, pre-swizzled.
// ---------------------------------------------------------------------------
__global__ void pack_w(const float* __restrict__ lin_w) {
    int idx = blockIdx.x * blockDim.x + threadIdx.x;
    if (idx >= COUT * JTOT) return;
    int o = idx / JTOT;
    int jp = idx % JTOT;
    int w = jp & 15;
    int c = jp >> 4;
    float v = 0.f;
    if (c < 64)      v = lin_w[o * 1072 + w * 67 + (c + 3)];
    else if (c < 67) v = lin_w[o * 1072 + w * 67 + (c - 64)];
    __nv_bfloat16 hi = __float2bfloat16(v);
    __nv_bfloat16 lo = __float2bfloat16(v - __bfloat162float(hi));
    int q  = jp >> 6;
    int jl = jp & 63;
    u32 off = (u32)(o * 128 + jl * 2);
    u32 pos = sw128(off) >> 1;
    g_w_hi[q * 8192 + pos] = hi;
    g_w_lo[q * 8192 + pos] = lo;
}

// ---------------------------------------------------------------------------
// pack_feats: channel-last padded rows g_feats[(b*N+n)*68 + c]
// ---------------------------------------------------------------------------
__global__ void pack_feats(const float* __restrict__ xyz, const float* __restrict__ feat) {
    int n = blockIdx.x * blockDim.x + threadIdx.x;
    int bc = blockIdx.y;
    int b = bc / CP;
    int c = bc % CP;
    if (n >= N_) return;
    float v = 0.f;
    if (c < 64)      v = feat[(b * CIN + c) * N_ + n];
    else if (c < 67) v = xyz[(b * 3 + (c - 64)) * N_ + n];
    g_feats[(b * N_ + n) * CP + c] = v;
}

// ---------------------------------------------------------------------------
// Main kernel: 128 points/block, 256 threads, ldmatrix + mma.sync bf16 hi/lo,
// software-pipelined: phase-2 compute for chunk q+1 interleaved with MMA(q).
// ---------------------------------------------------------------------------
extern __shared__ char s_raw[];

__global__ __launch_bounds__(256, 1)
void pointconv_main(const float* __restrict__ xyz, const int* __restrict__ knn,
                    const float* __restrict__ w1, const float* __restrict__ b1,
                    const float* __restrict__ w2, const float* __restrict__ b2,
                    const float* __restrict__ lin_b, float* __restrict__ out)
{
    const u32 sbase = s2u(s_raw);
    float* wk_s  = (float*)(s_raw + WK_OFF);
    int*   gid_s = (int*)(s_raw + GID_OFF);

    const int tid = threadIdx.x;
    const int wid = tid >> 5;
    const int lid = tid & 31;
    const int p0  = blockIdx.x * MT;
    const int b   = p0 / N_;
    const int n0  = p0 % N_;

    // ---------------- Phase 1: weight MLP, 8 (m,k) pairs per thread ------------------
    {
        const int m  = tid >> 1;
        const int kh = (tid & 1) * 8;
        const int n  = n0 + m;
        const float cx0 = xyz[(b * 3 + 0) * N_ + n];
        const float cx1 = xyz[(b * 3 + 1) * N_ + n];
        const float cx2 = xyz[(b * 3 + 2) * N_ + n];
        #pragma unroll
        for (int kk = 0; kk < 8; kk++) {
            const int k = kh + kk;
            const int idx = knn[(b * N_ + n) * KNN + k];
            gid_s[m * KNN + k] = (b * N_ + idx) * CP;
            const float d0 = xyz[(b * 3 + 0) * N_ + idx] - cx0;
            const float d1 = xyz[(b * 3 + 1) * N_ + idx] - cx1;
            const float d2 = xyz[(b * 3 + 2) * N_ + idx] - cx2;
            float h[8];
            #pragma unroll
            for (int o = 0; o < 8; o++) {
                float s = fmaf(w1[o * 3 + 0], d0,
                          fmaf(w1[o * 3 + 1], d1,
                          fmaf(w1[o * 3 + 2], d2, b1[o])));
                h[o] = leaky(s);
            }
            float wv[16];
            #pragma unroll
            for (int o = 0; o < 16; o++) {
                float s = b2[o];
                #pragma unroll
                for (int hh = 0; hh < 8; hh++) s = fmaf(w2[o * 8 + hh], h[hh], s);
                wv[o] = leaky(s);
            }
            float* dst = &wk_s[m * WK_STRIDE + k * 16];
            *(float4*)(dst)      = make_float4(wv[0],  wv[1],  wv[2],  wv[3]);
            *(float4*)(dst + 4)  = make_float4(wv[4],  wv[5],  wv[6],  wv[7]);
            *(float4*)(dst + 8)  = make_float4(wv[8],  wv[9],  wv[10], wv[11]);
            *(float4*)(dst + 12) = make_float4(wv[12], wv[13], wv[14], wv[15]);
        }
    }
    __syncthreads();

    // per-thread phase-2 roles: one point m, one w-half
    const int m  = tid >> 1;
    const int wh = tid & 1;                  // w in [wh*8, wh*8+8)
    const int*   gidx = &gid_s[m * KNN];
    const float* wkm  = &wk_s[m * WK_STRIDE + wh * 8];

    // per-warp MMA tiling: 4 (m) x 2 (n) warps, each 32m x 64n
    const int wm = wid & 3;
    const int wn = wid >> 2;

    float accf[2][8][4];
    #pragma unroll
    for (int t = 0; t < 2; t++)
        #pragma unroll
        for (int nt = 0; nt < 8; nt++)
            #pragma unroll
            for (int r = 0; r < 4; r++) accf[t][nt][r] = 0.f;

    // lane-dependent ldmatrix address components
    const u32 a_row = (u32)((lid & 7) + ((lid >> 3) & 1) * 8);
    const u32 a_kb  = (u32)(((lid >> 4) & 1) * 16);
    const u32 b_row = (u32)((lid & 7) + ((lid >> 4) & 1) * 8);
    const u32 b_kb  = (u32)(((lid >> 3) & 1) * 16);

    // ---- prologue: W prefetch + phase-2 compute for chunk 0 ----
    uint4 wreg[8];
    {
        const uint4* srch = (const uint4*)g_w_hi;
        const uint4* srcl = (const uint4*)g_w_lo;
        #pragma unroll
        for (int i = 0; i < 4; i++) {
            wreg[i]     = srch[tid + i * 256];
            wreg[4 + i] = srcl[tid + i * 256];
        }
    }
    u64 acc2[4][4];
    #pragma unroll
    for (int c = 0; c < 4; c++)
        #pragma unroll
        for (int p = 0; p < 4; p++) acc2[c][p] = 0ULL;
    #pragma unroll
    for (int k = 0; k < KNN; k++) {
        const float4 f = *(const float4*)&g_feats[gidx[k]];
        const ulonglong2 wa = *(const ulonglong2*)&wkm[k * 16];
        const ulonglong2 wb = *(const ulonglong2*)&wkm[k * 16 + 4];
        const u64 wp4[4] = {wa.x, wa.y, wb.x, wb.y};
        const u64 fc[4] = {pack2(f.x, f.x), pack2(f.y, f.y),
                           pack2(f.z, f.z), pack2(f.w, f.w)};
        #pragma unroll
        for (int c = 0; c < 4; c++)
            #pragma unroll
            for (int p = 0; p < 4; p++)
                acc2[c][p] = fma2(wp4[p], fc[c], acc2[c][p]);
    }

    // ---------------- Chunk loop (software-pipelined) ---------------------------------
    for (int q = 0; q < NCHUNK; q++) {
        // ---- store A tiles (bf16 hi/lo split) and W tiles for chunk q ----
        #pragma unroll
        for (int c = 0; c < 4; c++) {
            u32 hw[4], lw[4];
            #pragma unroll
            for (int p = 0; p < 4; p++) {
                const float2 f2 = unpack2(acc2[c][p]);
                __nv_bfloat162 h2 = __floats2bfloat162_rn(f2.x, f2.y);
                const float rx = f2.x - __bfloat162float(h2.x);
                const float ry = f2.y - __bfloat162float(h2.y);
                __nv_bfloat162 l2 = __floats2bfloat162_rn(rx, ry);
                hw[p] = *(u32*)&h2;
                lw[p] = *(u32*)&l2;
            }
            const u32 off = sw128((u32)(m * 128 + c * 32 + wh * 16));
            *(uint4*)(s_raw + A_HI_OFF + off) = make_uint4(hw[0], hw[1], hw[2], hw[3]);
            *(uint4*)(s_raw + A_LO_OFF + off) = make_uint4(lw[0], lw[1], lw[2], lw[3]);
        }
        {
            uint4* dsth = (uint4*)(s_raw + W_HI_OFF);
            uint4* dstl = (uint4*)(s_raw + W_LO_OFF);
            #pragma unroll
            for (int i = 0; i < 4; i++) {
                dsth[tid + i * 256] = wreg[i];
                dstl[tid + i * 256] = wreg[4 + i];
            }
        }
        __syncthreads();

        const bool more = (q + 1 < NCHUNK);
        const int  cbn  = 4 * (q + 1);

        // prefetch next W tiles (LDG latency hides under MMA)
        if (more) {
            const uint4* srch = (const uint4*)g_w_hi + (q + 1) * 1024;
            const uint4* srcl = (const uint4*)g_w_lo + (q + 1) * 1024;
            #pragma unroll
            for (int i = 0; i < 4; i++) {
                wreg[i]     = srch[tid + i * 256];
                wreg[4 + i] = srcl[tid + i * 256];
            }
        }

        // next-chunk accumulators
        u64 nacc[4][4];
        #pragma unroll
        for (int c = 0; c < 4; c++)
            #pragma unroll
            for (int p = 0; p < 4; p++) nacc[c][p] = 0ULL;

        // ---- interleaved: MMA(q) on tensor pipe + phase-2(q+1) on fma/L1 pipes ----
        #pragma unroll
        for (int ks = 0; ks < 4; ks++) {
            u32 ah[2][4], al[2][4];
            #pragma unroll
            for (int t = 0; t < 2; t++) {
                const u32 mr = (u32)(wm * 32 + t * 16) + a_row;
                const u32 o_sw = sw128(mr * 128 + (u32)(ks * 32) + a_kb);
                ldsm4(ah[t], sbase + A_HI_OFF + o_sw);
                ldsm4(al[t], sbase + A_LO_OFF + o_sw);
            }
            #pragma unroll
            for (int ng = 0; ng < 4; ng++) {
                const u32 orow = (u32)(wn * 64 + ng * 16) + b_row;
                const u32 o_sw = sw128(orow * 128 + (u32)(ks * 32) + b_kb);
                u32 bh[4], bl[4];
                ldsm4(bh, sbase + W_HI_OFF + o_sw);
                ldsm4(bl, sbase + W_LO_OFF + o_sw);
                #pragma unroll
                for (int t = 0; t < 2; t++) {
                    float* c0 = accf[t][ng * 2];
                    float* c1 = accf[t][ng * 2 + 1];
                    mma_bf16(c0, ah[t], bh[0], bh[1]);
                    mma_bf16(c0, ah[t], bl[0], bl[1]);
                    mma_bf16(c0, al[t], bh[0], bh[1]);
                    mma_bf16(c1, ah[t], bh[2], bh[3]);
                    mma_bf16(c1, ah[t], bl[2], bl[3]);
                    mma_bf16(c1, al[t], bh[2], bh[3]);
                }
                // one phase-2 k-iteration for chunk q+1
                if (more) {
                    const int k = ks * 4 + ng;
                    const float4 f = *(const float4*)&g_feats[gidx[k] + cbn];
                    const ulonglong2 wa = *(const ulonglong2*)&wkm[k * 16];
                    const ulonglong2 wb = *(const ulonglong2*)&wkm[k * 16 + 4];
                    const u64 wp4[4] = {wa.x, wa.y, wb.x, wb.y};
                    const u64 fc[4] = {pack2(f.x, f.x), pack2(f.y, f.y),
                                       pack2(f.z, f.z), pack2(f.w, f.w)};
                    #pragma unroll
                    for (int c = 0; c < 4; c++)
                        #pragma unroll
                        for (int p = 0; p < 4; p++)
                            nacc[c][p] = fma2(wp4[p], fc[c], nacc[c][p]);
                }
            }
        }
        __syncthreads();

        // rotate next-chunk accumulators in
        #pragma unroll
        for (int c = 0; c < 4; c++)
            #pragma unroll
            for (int p = 0; p < 4; p++) acc2[c][p] = nacc[c][p];
    }

    // ---------------- Epilogue: stage via smem, coalesced store ----------------------
    float* stage = wk_s;     // reuse
    {
        const int qr = lid >> 2;
        const int qc = 2 * (lid & 3);
        #pragma unroll
        for (int t = 0; t < 2; t++) {
            const int mr = wm * 32 + t * 16 + qr;
            #pragma unroll
            for (int nt = 0; nt < 8; nt++) {
                const int oc = wn * 64 + nt * 8 + qc;
                *(float2*)&stage[mr * STAGE_STRIDE + oc] =
                    make_float2(accf[t][nt][0], accf[t][nt][1]);
                *(float2*)&stage[(mr + 8) * STAGE_STRIDE + oc] =
                    make_float2(accf[t][nt][2], accf[t][nt][3]);
            }
        }
    }
    __syncthreads();
    {
        #pragma unroll
        for (int ow = 0; ow < 16; ow++) {
            const int o = wid * 16 + ow;
            const float bias = lin_b[o];
            float* orow = &out[(b * COUT + o) * N_ + n0];
            #pragma unroll
            for (int i = 0; i < 4; i++) {
                const int mm = lid + 32 * i;
                orow[mm] = leaky(stage[mm * STAGE_STRIDE + o] + bias);
            }
        }
    }
}

// ---------------------------------------------------------------------------
extern "C" void kernel_launch(void* const* d_in, const int* in_sizes, int n_in,
                              void* d_out, int out_size)
{
    const float* xyz  = (const float*)d_in[0];
    const float* feat = (const float*)d_in[1];
    const int*   knn  = (const int*)d_in[2];
    const float* w1   = (const float*)d_in[3];
    const float* b1   = (const float*)d_in[4];
    const float* w2   = (const float*)d_in[5];
    const float* b2   = (const float*)d_in[6];
    const float* lw   = (const float*)d_in[7];
    const float* lb   = (const float*)d_in[8];
    float* out = (float*)d_out;

    cudaFuncSetAttribute(pointconv_main, cudaFuncAttributeMaxDynamicSharedMemorySize, SMEM_TOTAL);

    pack_w<<<(COUT * JTOT + 255) / 256, 256>>>(lw);

    dim3 gp((N_ + 255) / 256, B_ * CP);
    pack_feats<<<gp, 256>>>(xyz, feat);

    pointconv_main<<<(B_ * N_) / MT, 256, SMEM_TOTAL>>>(xyz, knn, w1, b1, w2, b2, lb, out);
}

// round 9
// speedup vs baseline: 1.6512x; 1.6512x over previous
#include <cuda_runtime.h>
#include <cuda_bf16.h>

typedef unsigned int       u32;
typedef unsigned long long u64;

// Problem constants
#define B_     4
#define N_     16384
#define KNN    16
#define CIN    64
#define CP     68
#define JTOT   1088           // j' = c*16 + w
#define NCHUNK 17             // 17 chunks of 64 j'
#define COUT   128
#define MT     64             // points per block
#define NEG_SLOPE 0.1f
#define WK_STRIDE 260

// smem byte offsets
#define A_HI_OFF   0                            // 64x64 bf16 = 8192 B
#define A_LO_OFF   8192
#define WK_OFF     16384                        // float[64][260] = 66560 B
#define GID_OFF    (WK_OFF + 66560)             // int[64*16] = 4096 B
#define SMEM_TOTAL (GID_OFF + 4096)             // 87040 B  -> 2 CTAs/SM

#define STAGE_STRIDE 132

// Static device scratch
__device__ __align__(16) float g_feats[B_ * N_ * CP];
// W in mma-fragment layout: [q][wn][ks][ng][lane][4 u32], hi and lo planes
__device__ __align__(16) u32   g_wfh[NCHUNK * 4 * 4 * 2 * 32 * 4];
__device__ __align__(16) u32   g_wfl[NCHUNK * 4 * 4 * 2 * 32 * 4];

__device__ __forceinline__ float leaky(float x) { return x >= 0.f ? x : NEG_SLOPE * x; }

// ---- helpers ----------------------------------------------------------------
__device__ __forceinline__ u32 s2u(const void* p) {
    u32 a;
    asm("{ .reg .u64 t; cvta.to.shared.u64 t, %1; cvt.u32.u64 %0, t; }" : "=r"(a) : "l"(p));
    return a;
}
__device__ __forceinline__ u64 fma2(u64 a, u64 b, u64 c) {
    u64 d; asm("fma.rn.f32x2 %0, %1, %2, %3;" : "=l"(d) : "l"(a), "l"(b), "l"(c)); return d;
}
__device__ __forceinline__ u64 pack2(float x, float y) {
    u64 d; asm("mov.b64 %0, {%1, %2};" : "=l"(d) : "f"(x), "f"(y)); return d;
}
__device__ __forceinline__ float2 unpack2(u64 v) {
    float2 r; asm("mov.b64 {%0, %1}, %2;" : "=f"(r.x), "=f"(r.y) : "l"(v)); return r;
}
__device__ __forceinline__ u32 sw128(u32 off) { return off ^ ((off >> 3) & 0x70); }

__device__ __forceinline__ void ldsm4(u32* r, u32 addr) {
    asm volatile("ldmatrix.sync.aligned.m8n8.x4.shared.b16 {%0,%1,%2,%3}, [%4];"
                 : "=r"(r[0]), "=r"(r[1]), "=r"(r[2]), "=r"(r[3]) : "r"(addr));
}
__device__ __forceinline__ void mma_bf16(float* c, const u32* a, u32 b0, u32 b1) {
    asm volatile("mma.sync.aligned.m16n8k16.row.col.f32.bf16.bf16.f32 "
                 "{%0,%1,%2,%3}, {%4,%5,%6,%7}, {%8,%9}, {%0,%1,%2,%3};"
                 : "+f"(c[0]), "+f"(c[1]), "+f"(c[2]), "+f"(c[3])
                 : "r"(a[0]), "r"(a[1]), "r"(a[2]), "r"(a[3]), "r"(b0), "r"(b1));
}

// ---------------------------------------------------------------------------
// pack_wfrag: lin_w -> mma B-fragment layout (hi/lo bf16), j' = c*16 + w.
// One thread per packed u32 (2 bf16 along k).
// ---------------------------------------------------------------------------
__global__ void pack_wfrag(const float* __restrict__ lin_w) {
    int idx = blockIdx.x * blockDim.x + threadIdx.x;     // 0..69631
    if (idx >= NCHUNK * 4096) return;
    const int r    = idx & 3;
    const int lane = (idx >> 2) & 31;
    const int ng   = (idx >> 7) & 1;
    const int ks   = (idx >> 8) & 3;
    const int wn   = (idx >> 10) & 3;
    const int q    = idx >> 12;

    const int o = wn * 32 + ng * 16 + (r >> 1) * 8 + (lane >> 2);
    __nv_bfloat16 hi2[2], lo2[2];
    #pragma unroll
    for (int i = 0; i < 2; i++) {
        const int k16 = (r & 1) * 8 + 2 * (lane & 3) + i;
        const int jp  = q * 64 + ks * 16 + k16;
        const int w   = jp & 15;
        const int c   = jp >> 4;
        float v = 0.f;
        if (c < 64)      v = lin_w[o * 1072 + w * 67 + (c + 3)];
        else if (c < 67) v = lin_w[o * 1072 + w * 67 + (c - 64)];
        hi2[i] = __float2bfloat16(v);
        lo2[i] = __float2bfloat16(v - __bfloat162float(hi2[i]));
    }
    u32 hw, lw;
    {
        __nv_bfloat162 h = make_bfloat162(hi2[0], hi2[1]);
        __nv_bfloat162 l = make_bfloat162(lo2[0], lo2[1]);
        hw = *(u32*)&h;
        lw = *(u32*)&l;
    }
    g_wfh[idx] = hw;
    g_wfl[idx] = lw;
}

// ---------------------------------------------------------------------------
// pack_feats: channel-last padded rows g_feats[(b*N+n)*68 + c]
// ---------------------------------------------------------------------------
__global__ void pack_feats(const float* __restrict__ xyz, const float* __restrict__ feat) {
    int n = blockIdx.x * blockDim.x + threadIdx.x;
    int bc = blockIdx.y;
    int b = bc / CP;
    int c = bc % CP;
    if (n >= N_) return;
    float v = 0.f;
    if (c < 64)      v = feat[(b * CIN + c) * N_ + n];
    else if (c < 67) v = xyz[(b * 3 + (c - 64)) * N_ + n];
    g_feats[(b * N_ + n) * CP + c] = v;
}

// ---------------------------------------------------------------------------
// Main kernel: 64 points/block, 256 threads, 2 CTAs/SM.
// ---------------------------------------------------------------------------
extern __shared__ char s_raw[];

__global__ __launch_bounds__(256, 2)
void pointconv_main(const float* __restrict__ xyz, const int* __restrict__ knn,
                    const float* __restrict__ w1, const float* __restrict__ b1,
                    const float* __restrict__ w2, const float* __restrict__ b2,
                    const float* __restrict__ lin_b, float* __restrict__ out)
{
    const u32 sbase = s2u(s_raw);
    float* wk_s  = (float*)(s_raw + WK_OFF);
    int*   gid_s = (int*)(s_raw + GID_OFF);

    const int tid = threadIdx.x;
    const int wid = tid >> 5;
    const int lid = tid & 31;
    const int p0  = blockIdx.x * MT;
    const int b   = p0 / N_;
    const int n0  = p0 % N_;

    // ---------------- Phase 1: weight MLP, 4 (m,k) pairs per thread ------------------
    {
        const int m  = tid >> 2;               // 0..63
        const int kh = (tid & 3) * 4;
        const int n  = n0 + m;
        const float cx0 = xyz[(b * 3 + 0) * N_ + n];
        const float cx1 = xyz[(b * 3 + 1) * N_ + n];
        const float cx2 = xyz[(b * 3 + 2) * N_ + n];
        #pragma unroll
        for (int kk = 0; kk < 4; kk++) {
            const int k = kh + kk;
            const int idx = knn[(b * N_ + n) * KNN + k];
            gid_s[m * KNN + k] = (b * N_ + idx) * CP;
            const float d0 = xyz[(b * 3 + 0) * N_ + idx] - cx0;
            const float d1 = xyz[(b * 3 + 1) * N_ + idx] - cx1;
            const float d2 = xyz[(b * 3 + 2) * N_ + idx] - cx2;
            float h[8];
            #pragma unroll
            for (int o = 0; o < 8; o++) {
                float s = fmaf(w1[o * 3 + 0], d0,
                          fmaf(w1[o * 3 + 1], d1,
                          fmaf(w1[o * 3 + 2], d2, b1[o])));
                h[o] = leaky(s);
            }
            float wv[16];
            #pragma unroll
            for (int o = 0; o < 16; o++) {
                float s = b2[o];
                #pragma unroll
                for (int hh = 0; hh < 8; hh++) s = fmaf(w2[o * 8 + hh], h[hh], s);
                wv[o] = leaky(s);
            }
            float* dst = &wk_s[m * WK_STRIDE + k * 16];
            *(float4*)(dst)      = make_float4(wv[0],  wv[1],  wv[2],  wv[3]);
            *(float4*)(dst + 4)  = make_float4(wv[4],  wv[5],  wv[6],  wv[7]);
            *(float4*)(dst + 8)  = make_float4(wv[8],  wv[9],  wv[10], wv[11]);
            *(float4*)(dst + 12) = make_float4(wv[12], wv[13], wv[14], wv[15]);
        }
    }
    __syncthreads();

    // per-thread phase-2 role: point m, one channel per chunk (ch)
    const int m  = tid >> 2;                  // 0..63
    const int ch = tid & 3;
    const int*   gidx = &gid_s[m * KNN];
    const float* wkm  = &wk_s[m * WK_STRIDE];

    // per-warp MMA tiling: 2 (m) x 4 (n) warps, each 32m x 32n
    const int wm = wid & 1;
    const int wn = wid >> 1;

    float accf[2][4][4];
    #pragma unroll
    for (int t = 0; t < 2; t++)
        #pragma unroll
        for (int nt = 0; nt < 4; nt++)
            #pragma unroll
            for (int r = 0; r < 4; r++) accf[t][nt][r] = 0.f;

    // lane-dependent ldmatrix address components (A operand)
    const u32 a_row = (u32)((lid & 7) + ((lid >> 3) & 1) * 8);
    const u32 a_kb  = (u32)(((lid >> 4) & 1) * 16);

    // ---- prologue: phase-2 compute for chunk 0 ----
    u64 acc2[8];
    #pragma unroll
    for (int p = 0; p < 8; p++) acc2[p] = 0ULL;
    #pragma unroll
    for (int k = 0; k < KNN; k++) {
        const float f = g_feats[gidx[k] + ch];
        const u64 fb = pack2(f, f);
        const ulonglong2 wa = *(const ulonglong2*)&wkm[k * 16];
        const ulonglong2 wb = *(const ulonglong2*)&wkm[k * 16 + 4];
        const ulonglong2 wc = *(const ulonglong2*)&wkm[k * 16 + 8];
        const ulonglong2 wd = *(const ulonglong2*)&wkm[k * 16 + 12];
        acc2[0] = fma2(wa.x, fb, acc2[0]); acc2[1] = fma2(wa.y, fb, acc2[1]);
        acc2[2] = fma2(wb.x, fb, acc2[2]); acc2[3] = fma2(wb.y, fb, acc2[3]);
        acc2[4] = fma2(wc.x, fb, acc2[4]); acc2[5] = fma2(wc.y, fb, acc2[5]);
        acc2[6] = fma2(wd.x, fb, acc2[6]); acc2[7] = fma2(wd.y, fb, acc2[7]);
    }

    // ---------------- Chunk loop --------------------------------------------------
    for (int q = 0; q < NCHUNK; q++) {
        // ---- store A tile (bf16 hi/lo split): 16 w values = 32 bytes ----
        {
            u32 hw[8], lw[8];
            #pragma unroll
            for (int p = 0; p < 8; p++) {
                const float2 f2 = unpack2(acc2[p]);
                __nv_bfloat162 h2 = __floats2bfloat162_rn(f2.x, f2.y);
                const float rx = f2.x - __bfloat162float(h2.x);
                const float ry = f2.y - __bfloat162float(h2.y);
                __nv_bfloat162 l2 = __floats2bfloat162_rn(rx, ry);
                hw[p] = *(u32*)&h2;
                lw[p] = *(u32*)&l2;
            }
            const u32 off0 = sw128((u32)(m * 128 + ch * 32));
            const u32 off1 = sw128((u32)(m * 128 + ch * 32 + 16));
            *(uint4*)(s_raw + A_HI_OFF + off0) = make_uint4(hw[0], hw[1], hw[2], hw[3]);
            *(uint4*)(s_raw + A_HI_OFF + off1) = make_uint4(hw[4], hw[5], hw[6], hw[7]);
            *(uint4*)(s_raw + A_LO_OFF + off0) = make_uint4(lw[0], lw[1], lw[2], lw[3]);
            *(uint4*)(s_raw + A_LO_OFF + off1) = make_uint4(lw[4], lw[5], lw[6], lw[7]);
        }
        __syncthreads();

        // ---- MMA(q): A from smem (ldsm), B fragments straight from gmem/L2 ----
        {
            const uint4* wfh = (const uint4*)g_wfh + ((q * 4 + wn) * 4) * 2 * 32;
            const uint4* wfl = (const uint4*)g_wfl + ((q * 4 + wn) * 4) * 2 * 32;
            #pragma unroll
            for (int ks = 0; ks < 4; ks++) {
                const uint4 bh0 = wfh[(ks * 2 + 0) * 32 + lid];
                const uint4 bl0 = wfl[(ks * 2 + 0) * 32 + lid];
                const uint4 bh1 = wfh[(ks * 2 + 1) * 32 + lid];
                const uint4 bl1 = wfl[(ks * 2 + 1) * 32 + lid];
                u32 ah[2][4], al[2][4];
                #pragma unroll
                for (int t = 0; t < 2; t++) {
                    const u32 mr = (u32)(wm * 32 + t * 16) + a_row;
                    const u32 o_sw = sw128(mr * 128 + (u32)(ks * 32) + a_kb);
                    ldsm4(ah[t], sbase + A_HI_OFF + o_sw);
                    ldsm4(al[t], sbase + A_LO_OFF + o_sw);
                }
                #pragma unroll
                for (int t = 0; t < 2; t++) {
                    float* c00 = accf[t][0];
                    float* c01 = accf[t][1];
                    float* c10 = accf[t][2];
                    float* c11 = accf[t][3];
                    mma_bf16(c00, ah[t], bh0.x, bh0.y);
                    mma_bf16(c00, ah[t], bl0.x, bl0.y);
                    mma_bf16(c00, al[t], bh0.x, bh0.y);
                    mma_bf16(c01, ah[t], bh0.z, bh0.w);
                    mma_bf16(c01, ah[t], bl0.z, bl0.w);
                    mma_bf16(c01, al[t], bh0.z, bh0.w);
                    mma_bf16(c10, ah[t], bh1.x, bh1.y);
                    mma_bf16(c10, ah[t], bl1.x, bl1.y);
                    mma_bf16(c10, al[t], bh1.x, bh1.y);
                    mma_bf16(c11, ah[t], bh1.z, bh1.w);
                    mma_bf16(c11, ah[t], bl1.z, bl1.w);
                    mma_bf16(c11, al[t], bh1.z, bh1.w);
                }
            }
        }
        __syncthreads();

        // ---- phase-2 compute for chunk q+1 ----
        if (q + 1 < NCHUNK) {
            const int cidx = 4 * (q + 1) + ch;
            #pragma unroll
            for (int p = 0; p < 8; p++) acc2[p] = 0ULL;
            #pragma unroll
            for (int k = 0; k < KNN; k++) {
                const float f = g_feats[gidx[k] + cidx];
                const u64 fb = pack2(f, f);
                const ulonglong2 wa = *(const ulonglong2*)&wkm[k * 16];
                const ulonglong2 wb = *(const ulonglong2*)&wkm[k * 16 + 4];
                const ulonglong2 wc = *(const ulonglong2*)&wkm[k * 16 + 8];
                const ulonglong2 wd = *(const ulonglong2*)&wkm[k * 16 + 12];
                acc2[0] = fma2(wa.x, fb, acc2[0]); acc2[1] = fma2(wa.y, fb, acc2[1]);
                acc2[2] = fma2(wb.x, fb, acc2[2]); acc2[3] = fma2(wb.y, fb, acc2[3]);
                acc2[4] = fma2(wc.x, fb, acc2[4]); acc2[5] = fma2(wc.y, fb, acc2[5]);
                acc2[6] = fma2(wd.x, fb, acc2[6]); acc2[7] = fma2(wd.y, fb, acc2[7]);
            }
        }
    }

    // ---------------- Epilogue: stage via smem, coalesced store ----------------------
    float* stage = wk_s;     // reuse
    {
        const int qr = lid >> 2;
        const int qc = 2 * (lid & 3);
        #pragma unroll
        for (int t = 0; t < 2; t++) {
            const int mr = wm * 32 + t * 16 + qr;
            #pragma unroll
            for (int nt = 0; nt < 4; nt++) {
                const int oc = wn * 32 + nt * 8 + qc;
                *(float2*)&stage[mr * STAGE_STRIDE + oc] =
                    make_float2(accf[t][nt][0], accf[t][nt][1]);
                *(float2*)&stage[(mr + 8) * STAGE_STRIDE + oc] =
                    make_float2(accf[t][nt][2], accf[t][nt][3]);
            }
        }
    }
    __syncthreads();
    {
        #pragma unroll
        for (int ow = 0; ow < 16; ow++) {
            const int o = wid * 16 + ow;
            const float bias = lin_b[o];
            float* orow = &out[(b * COUT + o) * N_ + n0];
            #pragma unroll
            for (int i = 0; i < 2; i++) {
                const int mm = lid + 32 * i;
                orow[mm] = leaky(stage[mm * STAGE_STRIDE + o] + bias);
            }
        }
    }
}

// ---------------------------------------------------------------------------
extern "C" void kernel_launch(void* const* d_in, const int* in_sizes, int n_in,
                              void* d_out, int out_size)
{
    const float* xyz  = (const float*)d_in[0];
    const float* feat = (const float*)d_in[1];
    const int*   knn  = (const int*)d_in[2];
    const float* w1   = (const float*)d_in[3];
    const float* b1   = (const float*)d_in[4];
    const float* w2   = (const float*)d_in[5];
    const float* b2   = (const float*)d_in[6];
    const float* lw   = (const float*)d_in[7];
    const float* lb   = (const float*)d_in[8];
    float* out = (float*)d_out;

    cudaFuncSetAttribute(pointconv_main, cudaFuncAttributeMaxDynamicSharedMemorySize, SMEM_TOTAL);

    pack_wfrag<<<(NCHUNK * 4096 + 255) / 256, 256>>>(lw);

    dim3 gp((N_ + 255) / 256, B_ * CP);
    pack_feats<<<gp, 256>>>(xyz, feat);

    pointconv_main<<<(B_ * N_) / MT, 256, SMEM_TOTAL>>>(xyz, knn, w1, b1, w2, b2, lb, out);
}

// round 11
// speedup vs baseline: 2.1383x; 1.2950x over previous
#include <cuda_runtime.h>
#include <cuda_bf16.h>
#include <cuda_fp16.h>

typedef unsigned int       u32;
typedef unsigned long long u64;

// Problem constants
#define B_     4
#define N_     16384
#define KNN    16
#define CIN    64
#define CP     68
#define JTOT   1088           // j' = c*16 + w
#define NCHUNK 17             // 17 chunks of 64 j'
#define COUT   128
#define MT     64             // points per block
#define NEG_SLOPE 0.1f
#define WK_STRIDE 260

// smem byte offsets
#define A0_OFF     0                            // 64x64 fp16 tile, buffer 0 (8192 B)
#define A1_OFF     8192                         // buffer 1
#define WK_OFF     16384                        // float[64][260] = 66560 B
#define GID_OFF    (WK_OFF + 66560)             // int[64*16] = 4096 B
#define SMEM_TOTAL (GID_OFF + 4096)             // 87040 B -> 2 CTAs/SM

#define STAGE_STRIDE 132

// Static device scratch
__device__ __align__(16) float g_feats[B_ * N_ * CP];
// W in mma-fragment layout: [q][wn][ks][ng][lane][4 u32] (fp16x2 packed)
__device__ __align__(16) u32   g_wf[NCHUNK * 4 * 4 * 2 * 32 * 4];

__device__ __forceinline__ float leaky(float x) { return x >= 0.f ? x : NEG_SLOPE * x; }

// ---- helpers ----------------------------------------------------------------
__device__ __forceinline__ u32 s2u(const void* p) {
    u32 a;
    asm("{ .reg .u64 t; cvta.to.shared.u64 t, %1; cvt.u32.u64 %0, t; }" : "=r"(a) : "l"(p));
    return a;
}
__device__ __forceinline__ u64 fma2(u64 a, u64 b, u64 c) {
    u64 d; asm("fma.rn.f32x2 %0, %1, %2, %3;" : "=l"(d) : "l"(a), "l"(b), "l"(c)); return d;
}
__device__ __forceinline__ u64 pack2(float x, float y) {
    u64 d; asm("mov.b64 %0, {%1, %2};" : "=l"(d) : "f"(x), "f"(y)); return d;
}
__device__ __forceinline__ float2 unpack2(u64 v) {
    float2 r; asm("mov.b64 {%0, %1}, %2;" : "=f"(r.x), "=f"(r.y) : "l"(v)); return r;
}
__device__ __forceinline__ u32 sw128(u32 off) { return off ^ ((off >> 3) & 0x70); }

__device__ __forceinline__ void ldsm4(u32* r, u32 addr) {
    asm volatile("ldmatrix.sync.aligned.m8n8.x4.shared.b16 {%0,%1,%2,%3}, [%4];"
                 : "=r"(r[0]), "=r"(r[1]), "=r"(r[2]), "=r"(r[3]) : "r"(addr));
}
__device__ __forceinline__ void mma_f16(float* c, const u32* a, u32 b0, u32 b1) {
    asm volatile("mma.sync.aligned.m16n8k16.row.col.f32.f16.f16.f32 "
                 "{%0,%1,%2,%3}, {%4,%5,%6,%7}, {%8,%9}, {%0,%1,%2,%3};"
                 : "+f"(c[0]), "+f"(c[1]), "+f"(c[2]), "+f"(c[3])
                 : "r"(a[0]), "r"(a[1]), "r"(a[2]), "r"(a[3]), "r"(b0), "r"(b1));
}

// ---------------------------------------------------------------------------
// pack_wfrag: lin_w -> mma B-fragment layout (fp16), j' = c*16 + w.
// One thread per packed u32 (2 fp16 along k).
// ---------------------------------------------------------------------------
__global__ void pack_wfrag(const float* __restrict__ lin_w) {
    int idx = blockIdx.x * blockDim.x + threadIdx.x;     // 0..69631
    if (idx >= NCHUNK * 4096) return;
    const int r    = idx & 3;
    const int lane = (idx >> 2) & 31;
    const int ng   = (idx >> 7) & 1;
    const int ks   = (idx >> 8) & 3;
    const int wn   = (idx >> 10) & 3;
    const int q    = idx >> 12;

    const int o = wn * 32 + ng * 16 + (r >> 1) * 8 + (lane >> 2);
    float v[2];
    #pragma unroll
    for (int i = 0; i < 2; i++) {
        const int k16 = (r & 1) * 8 + 2 * (lane & 3) + i;
        const int jp  = q * 64 + ks * 16 + k16;
        const int w   = jp & 15;
        const int c   = jp >> 4;
        float x = 0.f;
        if (c < 64)      x = lin_w[o * 1072 + w * 67 + (c + 3)];
        else if (c < 67) x = lin_w[o * 1072 + w * 67 + (c - 64)];
        v[i] = x;
    }
    __half2 h = __floats2half2_rn(v[0], v[1]);
    g_wf[idx] = *(u32*)&h;
}

// ---------------------------------------------------------------------------
// pack_feats: channel-last padded rows g_feats[(b*N+n)*68 + c]
// ---------------------------------------------------------------------------
__global__ void pack_feats(const float* __restrict__ xyz, const float* __restrict__ feat) {
    int n = blockIdx.x * blockDim.x + threadIdx.x;
    int bc = blockIdx.y;
    int b = bc / CP;
    int c = bc % CP;
    if (n >= N_) return;
    float v = 0.f;
    if (c < 64)      v = feat[(b * CIN + c) * N_ + n];
    else if (c < 67) v = xyz[(b * 3 + (c - 64)) * N_ + n];
    g_feats[(b * N_ + n) * CP + c] = v;
}

// ---------------------------------------------------------------------------
// Main kernel: 64 points/block, 256 threads, 2 CTAs/SM, fp16 single-term MMA,
// double-buffered A tile -> one __syncthreads per chunk.
// ---------------------------------------------------------------------------
extern __shared__ char s_raw[];

__global__ __launch_bounds__(256, 2)
void pointconv_main(const float* __restrict__ xyz, const int* __restrict__ knn,
                    const float* __restrict__ w1, const float* __restrict__ b1,
                    const float* __restrict__ w2, const float* __restrict__ b2,
                    const float* __restrict__ lin_b, float* __restrict__ out)
{
    const u32 sbase = s2u(s_raw);
    float* wk_s  = (float*)(s_raw + WK_OFF);
    int*   gid_s = (int*)(s_raw + GID_OFF);

    const int tid = threadIdx.x;
    const int wid = tid >> 5;
    const int lid = tid & 31;
    const int p0  = blockIdx.x * MT;
    const int b   = p0 / N_;
    const int n0  = p0 % N_;

    // ---------------- Phase 1: weight MLP, 4 (m,k) pairs per thread ------------------
    {
        const int m  = tid >> 2;               // 0..63
        const int kh = (tid & 3) * 4;
        const int n  = n0 + m;
        const float cx0 = xyz[(b * 3 + 0) * N_ + n];
        const float cx1 = xyz[(b * 3 + 1) * N_ + n];
        const float cx2 = xyz[(b * 3 + 2) * N_ + n];
        #pragma unroll
        for (int kk = 0; kk < 4; kk++) {
            const int k = kh + kk;
            const int idx = knn[(b * N_ + n) * KNN + k];
            gid_s[m * KNN + k] = (b * N_ + idx) * CP;
            const float d0 = xyz[(b * 3 + 0) * N_ + idx] - cx0;
            const float d1 = xyz[(b * 3 + 1) * N_ + idx] - cx1;
            const float d2 = xyz[(b * 3 + 2) * N_ + idx] - cx2;
            float h[8];
            #pragma unroll
            for (int o = 0; o < 8; o++) {
                float s = fmaf(w1[o * 3 + 0], d0,
                          fmaf(w1[o * 3 + 1], d1,
                          fmaf(w1[o * 3 + 2], d2, b1[o])));
                h[o] = leaky(s);
            }
            float wv[16];
            #pragma unroll
            for (int o = 0; o < 16; o++) {
                float s = b2[o];
                #pragma unroll
                for (int hh = 0; hh < 8; hh++) s = fmaf(w2[o * 8 + hh], h[hh], s);
                wv[o] = leaky(s);
            }
            float* dst = &wk_s[m * WK_STRIDE + k * 16];
            *(float4*)(dst)      = make_float4(wv[0],  wv[1],  wv[2],  wv[3]);
            *(float4*)(dst + 4)  = make_float4(wv[4],  wv[5],  wv[6],  wv[7]);
            *(float4*)(dst + 8)  = make_float4(wv[8],  wv[9],  wv[10], wv[11]);
            *(float4*)(dst + 12) = make_float4(wv[12], wv[13], wv[14], wv[15]);
        }
    }
    __syncthreads();

    // per-thread phase-2 role: point m, one channel per chunk (ch)
    const int m  = tid >> 2;                  // 0..63
    const int ch = tid & 3;
    const int*   gidx = &gid_s[m * KNN];
    const float* wkm  = &wk_s[m * WK_STRIDE];

    // per-warp MMA tiling: 2 (m) x 4 (n) warps, each 32m x 32n
    const int wm = wid & 1;
    const int wn = wid >> 1;

    float accf[2][4][4];
    #pragma unroll
    for (int t = 0; t < 2; t++)
        #pragma unroll
        for (int nt = 0; nt < 4; nt++)
            #pragma unroll
            for (int r = 0; r < 4; r++) accf[t][nt][r] = 0.f;

    // lane-dependent ldmatrix address components (A operand)
    const u32 a_row = (u32)((lid & 7) + ((lid >> 3) & 1) * 8);
    const u32 a_kb  = (u32)(((lid >> 4) & 1) * 16);

    // ---- prologue: phase-2 compute for chunk 0 ----
    u64 acc2[8];
    #pragma unroll
    for (int p = 0; p < 8; p++) acc2[p] = 0ULL;
    #pragma unroll
    for (int k = 0; k < KNN; k++) {
        const float f = g_feats[gidx[k] + ch];
        const u64 fb = pack2(f, f);
        const ulonglong2 wa = *(const ulonglong2*)&wkm[k * 16];
        const ulonglong2 wb = *(const ulonglong2*)&wkm[k * 16 + 4];
        const ulonglong2 wc = *(const ulonglong2*)&wkm[k * 16 + 8];
        const ulonglong2 wd = *(const ulonglong2*)&wkm[k * 16 + 12];
        acc2[0] = fma2(wa.x, fb, acc2[0]); acc2[1] = fma2(wa.y, fb, acc2[1]);
        acc2[2] = fma2(wb.x, fb, acc2[2]); acc2[3] = fma2(wb.y, fb, acc2[3]);
        acc2[4] = fma2(wc.x, fb, acc2[4]); acc2[5] = fma2(wc.y, fb, acc2[5]);
        acc2[6] = fma2(wd.x, fb, acc2[6]); acc2[7] = fma2(wd.y, fb, acc2[7]);
    }

    // ---------------- Chunk loop (single barrier per chunk) --------------------------
    for (int q = 0; q < NCHUNK; q++) {
        const u32 abuf = (q & 1) ? (u32)A1_OFF : (u32)A0_OFF;

        // ---- store A tile (fp16): 16 w values = 32 bytes ----
        {
            u32 hw[8];
            #pragma unroll
            for (int p = 0; p < 8; p++) {
                const float2 f2 = unpack2(acc2[p]);
                __half2 h2 = __floats2half2_rn(f2.x, f2.y);
                hw[p] = *(u32*)&h2;
            }
            const u32 off0 = sw128((u32)(m * 128 + ch * 32));
            const u32 off1 = sw128((u32)(m * 128 + ch * 32 + 16));
            *(uint4*)(s_raw + abuf + off0) = make_uint4(hw[0], hw[1], hw[2], hw[3]);
            *(uint4*)(s_raw + abuf + off1) = make_uint4(hw[4], hw[5], hw[6], hw[7]);
        }
        __syncthreads();

        // ---- MMA(q): A from smem (ldsm), B fragments straight from gmem/L2 ----
        {
            const uint4* wf = (const uint4*)g_wf + ((q * 4 + wn) * 4) * 2 * 32;
            #pragma unroll
            for (int ks = 0; ks < 4; ks++) {
                const uint4 b0 = wf[(ks * 2 + 0) * 32 + lid];
                const uint4 b1 = wf[(ks * 2 + 1) * 32 + lid];
                u32 ah[2][4];
                #pragma unroll
                for (int t = 0; t < 2; t++) {
                    const u32 mr = (u32)(wm * 32 + t * 16) + a_row;
                    const u32 o_sw = sw128(mr * 128 + (u32)(ks * 32) + a_kb);
                    ldsm4(ah[t], sbase + abuf + o_sw);
                }
                #pragma unroll
                for (int t = 0; t < 2; t++) {
                    mma_f16(accf[t][0], ah[t], b0.x, b0.y);
                    mma_f16(accf[t][1], ah[t], b0.z, b0.w);
                    mma_f16(accf[t][2], ah[t], b1.x, b1.y);
                    mma_f16(accf[t][3], ah[t], b1.z, b1.w);
                }
            }
        }

        // ---- phase-2 compute for chunk q+1 (no barrier needed: other buffer) ----
        if (q + 1 < NCHUNK) {
            const int cidx = 4 * (q + 1) + ch;
            #pragma unroll
            for (int p = 0; p < 8; p++) acc2[p] = 0ULL;
            #pragma unroll
            for (int k = 0; k < KNN; k++) {
                const float f = g_feats[gidx[k] + cidx];
                const u64 fb = pack2(f, f);
                const ulonglong2 wa = *(const ulonglong2*)&wkm[k * 16];
                const ulonglong2 wb = *(const ulonglong2*)&wkm[k * 16 + 4];
                const ulonglong2 wc = *(const ulonglong2*)&wkm[k * 16 + 8];
                const ulonglong2 wd = *(const ulonglong2*)&wkm[k * 16 + 12];
                acc2[0] = fma2(wa.x, fb, acc2[0]); acc2[1] = fma2(wa.y, fb, acc2[1]);
                acc2[2] = fma2(wb.x, fb, acc2[2]); acc2[3] = fma2(wb.y, fb, acc2[3]);
                acc2[4] = fma2(wc.x, fb, acc2[4]); acc2[5] = fma2(wc.y, fb, acc2[5]);
                acc2[6] = fma2(wd.x, fb, acc2[6]); acc2[7] = fma2(wd.y, fb, acc2[7]);
            }
        }
    }

    // ---------------- Epilogue: stage via smem, coalesced store ----------------------
    __syncthreads();
    float* stage = wk_s;     // reuse
    {
        const int qr = lid >> 2;
        const int qc = 2 * (lid & 3);
        #pragma unroll
        for (int t = 0; t < 2; t++) {
            const int mr = wm * 32 + t * 16 + qr;
            #pragma unroll
            for (int nt = 0; nt < 4; nt++) {
                const int oc = wn * 32 + nt * 8 + qc;
                *(float2*)&stage[mr * STAGE_STRIDE + oc] =
                    make_float2(accf[t][nt][0], accf[t][nt][1]);
                *(float2*)&stage[(mr + 8) * STAGE_STRIDE + oc] =
                    make_float2(accf[t][nt][2], accf[t][nt][3]);
            }
        }
    }
    __syncthreads();
    {
        #pragma unroll
        for (int ow = 0; ow < 16; ow++) {
            const int o = wid * 16 + ow;
            const float bias = lin_b[o];
            float* orow = &out[(b * COUT + o) * N_ + n0];
            #pragma unroll
            for (int i = 0; i < 2; i++) {
                const int mm = lid + 32 * i;
                orow[mm] = leaky(stage[mm * STAGE_STRIDE + o] + bias);
            }
        }
    }
}

// ---------------------------------------------------------------------------
extern "C" void kernel_launch(void* const* d_in, const int* in_sizes, int n_in,
                              void* d_out, int out_size)
{
    const float* xyz  = (const float*)d_in[0];
    const float* feat = (const float*)d_in[1];
    const int*   knn  = (const int*)d_in[2];
    const float* w1   = (const float*)d_in[3];
    const float* b1   = (const float*)d_in[4];
    const float* w2   = (const float*)d_in[5];
    const float* b2   = (const float*)d_in[6];
    const float* lw   = (const float*)d_in[7];
    const float* lb   = (const float*)d_in[8];
    float* out = (float*)d_out;

    cudaFuncSetAttribute(pointconv_main, cudaFuncAttributeMaxDynamicSharedMemorySize, SMEM_TOTAL);

    pack_wfrag<<<(NCHUNK * 4096 + 255) / 256, 256>>>(lw);

    dim3 gp((N_ + 255) / 256, B_ * CP);
    pack_feats<<<gp, 256>>>(xyz, feat);

    pointconv_main<<<(B_ * N_) / MT, 256, SMEM_TOTAL>>>(xyz, knn, w1, b1, w2, b2, lb, out);
}

// round 13
// speedup vs baseline: 2.1419x; 1.0017x over previous
#include <cuda_runtime.h>
#include <cuda_bf16.h>
#include <cuda_fp16.h>

typedef unsigned int       u32;
typedef unsigned long long u64;

// Problem constants
#define B_     4
#define N_     16384
#define KNN    16
#define CIN    64
#define CP     68
#define JTOT   1088           // j' = c*16 + w
#define NCHUNK 17             // 17 chunks of 64 j'
#define COUT   128
#define MT     64             // points per block
#define NEG_SLOPE 0.1f
#define WK_STRIDE 260

// smem byte offsets
#define A0_OFF     0                            // 64x64 fp16 tile, buffer 0 (8192 B)
#define A1_OFF     8192                         // buffer 1
#define WK_OFF     16384                        // float[64][260] = 66560 B
#define GID_OFF    (WK_OFF + 66560)             // int[64*16] = 4096 B
#define SMEM_TOTAL (GID_OFF + 4096)             // 87040 B -> 2 CTAs/SM

#define STAGE_STRIDE 132

// Static device scratch
__device__ __align__(16) float g_feats[B_ * N_ * CP];
// W in mma-fragment layout: [q][wn][ks][ng][lane][4 u32] (fp16x2 packed)
__device__ __align__(16) u32   g_wf[NCHUNK * 4 * 4 * 2 * 32 * 4];

__device__ __forceinline__ float leaky(float x) { return x >= 0.f ? x : NEG_SLOPE * x; }

// ---- helpers ----------------------------------------------------------------
__device__ __forceinline__ u32 s2u(const void* p) {
    u32 a;
    asm("{ .reg .u64 t; cvta.to.shared.u64 t, %1; cvt.u32.u64 %0, t; }" : "=r"(a) : "l"(p));
    return a;
}
__device__ __forceinline__ u64 fma2(u64 a, u64 b, u64 c) {
    u64 d; asm("fma.rn.f32x2 %0, %1, %2, %3;" : "=l"(d) : "l"(a), "l"(b), "l"(c)); return d;
}
__device__ __forceinline__ u64 pack2(float x, float y) {
    u64 d; asm("mov.b64 %0, {%1, %2};" : "=l"(d) : "f"(x), "f"(y)); return d;
}
__device__ __forceinline__ float2 unpack2(u64 v) {
    float2 r; asm("mov.b64 {%0, %1}, %2;" : "=f"(r.x), "=f"(r.y) : "l"(v)); return r;
}
__device__ __forceinline__ u32 sw128(u32 off) { return off ^ ((off >> 3) & 0x70); }

__device__ __forceinline__ void ldsm4(u32* r, u32 addr) {
    asm volatile("ldmatrix.sync.aligned.m8n8.x4.shared.b16 {%0,%1,%2,%3}, [%4];"
                 : "=r"(r[0]), "=r"(r[1]), "=r"(r[2]), "=r"(r[3]) : "r"(addr));
}
__device__ __forceinline__ void mma_f16(float* c, const u32* a, u32 b0, u32 b1) {
    asm volatile("mma.sync.aligned.m16n8k16.row.col.f32.f16.f16.f32 "
                 "{%0,%1,%2,%3}, {%4,%5,%6,%7}, {%8,%9}, {%0,%1,%2,%3};"
                 : "+f"(c[0]), "+f"(c[1]), "+f"(c[2]), "+f"(c[3])
                 : "r"(a[0]), "r"(a[1]), "r"(a[2]), "r"(a[3]), "r"(b0), "r"(b1));
}

// ---------------------------------------------------------------------------
// pack_wfrag: lin_w -> mma B-fragment layout (fp16), j' = c*16 + w.
// One thread per packed u32 (2 fp16 along k).
// ---------------------------------------------------------------------------
__global__ void pack_wfrag(const float* __restrict__ lin_w) {
    int idx = blockIdx.x * blockDim.x + threadIdx.x;     // 0..69631
    if (idx >= NCHUNK * 4096) return;
    const int r    = idx & 3;
    const int lane = (idx >> 2) & 31;
    const int ng   = (idx >> 7) & 1;
    const int ks   = (idx >> 8) & 3;
    const int wn   = (idx >> 10) & 3;
    const int q    = idx >> 12;

    const int o = wn * 32 + ng * 16 + (r >> 1) * 8 + (lane >> 2);
    float v[2];
    #pragma unroll
    for (int i = 0; i < 2; i++) {
        const int k16 = (r & 1) * 8 + 2 * (lane & 3) + i;
        const int jp  = q * 64 + ks * 16 + k16;
        const int w   = jp & 15;
        const int c   = jp >> 4;
        float x = 0.f;
        if (c < 64)      x = lin_w[o * 1072 + w * 67 + (c + 3)];
        else if (c < 67) x = lin_w[o * 1072 + w * 67 + (c - 64)];
        v[i] = x;
    }
    __half2 h = __floats2half2_rn(v[0], v[1]);
    g_wf[idx] = *(u32*)&h;
}

// ---------------------------------------------------------------------------
// pack_feats: channel-last padded rows g_feats[(b*N+n)*68 + c]
// ---------------------------------------------------------------------------
__global__ void pack_feats(const float* __restrict__ xyz, const float* __restrict__ feat) {
    int n = blockIdx.x * blockDim.x + threadIdx.x;
    int bc = blockIdx.y;
    int b = bc / CP;
    int c = bc % CP;
    if (n >= N_) return;
    float v = 0.f;
    if (c < 64)      v = feat[(b * CIN + c) * N_ + n];
    else if (c < 67) v = xyz[(b * 3 + (c - 64)) * N_ + n];
    g_feats[(b * N_ + n) * CP + c] = v;
}

// ---------------------------------------------------------------------------
// Main kernel: 64 points/block, 256 threads, 2 CTAs/SM, fp16 single-term MMA,
// double-buffered A tile -> one __syncthreads per chunk.
// ---------------------------------------------------------------------------
extern __shared__ char s_raw[];

__global__ __launch_bounds__(256, 2)
void pointconv_main(const float* __restrict__ xyz, const int* __restrict__ knn,
                    const float* __restrict__ w1, const float* __restrict__ b1,
                    const float* __restrict__ w2, const float* __restrict__ b2,
                    const float* __restrict__ lin_b, float* __restrict__ out)
{
    const u32 sbase = s2u(s_raw);
    float* wk_s  = (float*)(s_raw + WK_OFF);
    int*   gid_s = (int*)(s_raw + GID_OFF);

    const int tid = threadIdx.x;
    const int wid = tid >> 5;
    const int lid = tid & 31;
    const int p0  = blockIdx.x * MT;
    const int b   = p0 / N_;
    const int n0  = p0 % N_;

    // ---------------- Phase 1: weight MLP, 4 (m,k) pairs per thread ------------------
    {
        const int m  = tid >> 2;               // 0..63
        const int kh = (tid & 3) * 4;
        const int n  = n0 + m;
        const float cx0 = xyz[(b * 3 + 0) * N_ + n];
        const float cx1 = xyz[(b * 3 + 1) * N_ + n];
        const float cx2 = xyz[(b * 3 + 2) * N_ + n];
        #pragma unroll
        for (int kk = 0; kk < 4; kk++) {
            const int k = kh + kk;
            const int idx = knn[(b * N_ + n) * KNN + k];
            gid_s[m * KNN + k] = (b * N_ + idx) * CP;
            const float d0 = xyz[(b * 3 + 0) * N_ + idx] - cx0;
            const float d1 = xyz[(b * 3 + 1) * N_ + idx] - cx1;
            const float d2 = xyz[(b * 3 + 2) * N_ + idx] - cx2;
            float h[8];
            #pragma unroll
            for (int o = 0; o < 8; o++) {
                float s = fmaf(w1[o * 3 + 0], d0,
                          fmaf(w1[o * 3 + 1], d1,
                          fmaf(w1[o * 3 + 2], d2, b1[o])));
                h[o] = leaky(s);
            }
            float wv[16];
            #pragma unroll
            for (int o = 0; o < 16; o++) {
                float s = b2[o];
                #pragma unroll
                for (int hh = 0; hh < 8; hh++) s = fmaf(w2[o * 8 + hh], h[hh], s);
                wv[o] = leaky(s);
            }
            float* dst = &wk_s[m * WK_STRIDE + k * 16];
            *(float4*)(dst)      = make_float4(wv[0],  wv[1],  wv[2],  wv[3]);
            *(float4*)(dst + 4)  = make_float4(wv[4],  wv[5],  wv[6],  wv[7]);
            *(float4*)(dst + 8)  = make_float4(wv[8],  wv[9],  wv[10], wv[11]);
            *(float4*)(dst + 12) = make_float4(wv[12], wv[13], wv[14], wv[15]);
        }
    }
    __syncthreads();

    // per-thread phase-2 role: point m, one channel per chunk (ch)
    const int m  = tid >> 2;                  // 0..63
    const int ch = tid & 3;
    const int*   gidx = &gid_s[m * KNN];
    const float* wkm  = &wk_s[m * WK_STRIDE];

    // per-warp MMA tiling: 2 (m) x 4 (n) warps, each 32m x 32n
    const int wm = wid & 1;
    const int wn = wid >> 1;

    float accf[2][4][4];
    #pragma unroll
    for (int t = 0; t < 2; t++)
        #pragma unroll
        for (int nt = 0; nt < 4; nt++)
            #pragma unroll
            for (int r = 0; r < 4; r++) accf[t][nt][r] = 0.f;

    // lane-dependent ldmatrix address components (A operand)
    const u32 a_row = (u32)((lid & 7) + ((lid >> 3) & 1) * 8);
    const u32 a_kb  = (u32)(((lid >> 4) & 1) * 16);

    // ---- prologue: phase-2 compute for chunk 0 ----
    u64 acc2[8];
    #pragma unroll
    for (int p = 0; p < 8; p++) acc2[p] = 0ULL;
    #pragma unroll
    for (int k = 0; k < KNN; k++) {
        const float f = g_feats[gidx[k] + ch];
        const u64 fb = pack2(f, f);
        const ulonglong2 wa = *(const ulonglong2*)&wkm[k * 16];
        const ulonglong2 wb = *(const ulonglong2*)&wkm[k * 16 + 4];
        const ulonglong2 wc = *(const ulonglong2*)&wkm[k * 16 + 8];
        const ulonglong2 wd = *(const ulonglong2*)&wkm[k * 16 + 12];
        acc2[0] = fma2(wa.x, fb, acc2[0]); acc2[1] = fma2(wa.y, fb, acc2[1]);
        acc2[2] = fma2(wb.x, fb, acc2[2]); acc2[3] = fma2(wb.y, fb, acc2[3]);
        acc2[4] = fma2(wc.x, fb, acc2[4]); acc2[5] = fma2(wc.y, fb, acc2[5]);
        acc2[6] = fma2(wd.x, fb, acc2[6]); acc2[7] = fma2(wd.y, fb, acc2[7]);
    }

    // ---------------- Chunk loop (single barrier per chunk) --------------------------
    for (int q = 0; q < NCHUNK; q++) {
        const u32 abuf = (q & 1) ? (u32)A1_OFF : (u32)A0_OFF;

        // ---- store A tile (fp16): 16 w values = 32 bytes ----
        {
            u32 hw[8];
            #pragma unroll
            for (int p = 0; p < 8; p++) {
                const float2 f2 = unpack2(acc2[p]);
                __half2 h2 = __floats2half2_rn(f2.x, f2.y);
                hw[p] = *(u32*)&h2;
            }
            const u32 off0 = sw128((u32)(m * 128 + ch * 32));
            const u32 off1 = sw128((u32)(m * 128 + ch * 32 + 16));
            *(uint4*)(s_raw + abuf + off0) = make_uint4(hw[0], hw[1], hw[2], hw[3]);
            *(uint4*)(s_raw + abuf + off1) = make_uint4(hw[4], hw[5], hw[6], hw[7]);
        }
        __syncthreads();

        // ---- MMA(q): A from smem (ldsm), B fragments straight from gmem/L2 ----
        {
            const uint4* wf = (const uint4*)g_wf + ((q * 4 + wn) * 4) * 2 * 32;
            #pragma unroll
            for (int ks = 0; ks < 4; ks++) {
                const uint4 b0 = wf[(ks * 2 + 0) * 32 + lid];
                const uint4 b1 = wf[(ks * 2 + 1) * 32 + lid];
                u32 ah[2][4];
                #pragma unroll
                for (int t = 0; t < 2; t++) {
                    const u32 mr = (u32)(wm * 32 + t * 16) + a_row;
                    const u32 o_sw = sw128(mr * 128 + (u32)(ks * 32) + a_kb);
                    ldsm4(ah[t], sbase + abuf + o_sw);
                }
                #pragma unroll
                for (int t = 0; t < 2; t++) {
                    mma_f16(accf[t][0], ah[t], b0.x, b0.y);
                    mma_f16(accf[t][1], ah[t], b0.z, b0.w);
                    mma_f16(accf[t][2], ah[t], b1.x, b1.y);
                    mma_f16(accf[t][3], ah[t], b1.z, b1.w);
                }
            }
        }

        // ---- phase-2 compute for chunk q+1 (no barrier needed: other buffer) ----
        if (q + 1 < NCHUNK) {
            const int cidx = 4 * (q + 1) + ch;
            #pragma unroll
            for (int p = 0; p < 8; p++) acc2[p] = 0ULL;
            #pragma unroll
            for (int k = 0; k < KNN; k++) {
                const float f = g_feats[gidx[k] + cidx];
                const u64 fb = pack2(f, f);
                const ulonglong2 wa = *(const ulonglong2*)&wkm[k * 16];
                const ulonglong2 wb = *(const ulonglong2*)&wkm[k * 16 + 4];
                const ulonglong2 wc = *(const ulonglong2*)&wkm[k * 16 + 8];
                const ulonglong2 wd = *(const ulonglong2*)&wkm[k * 16 + 12];
                acc2[0] = fma2(wa.x, fb, acc2[0]); acc2[1] = fma2(wa.y, fb, acc2[1]);
                acc2[2] = fma2(wb.x, fb, acc2[2]); acc2[3] = fma2(wb.y, fb, acc2[3]);
                acc2[4] = fma2(wc.x, fb, acc2[4]); acc2[5] = fma2(wc.y, fb, acc2[5]);
                acc2[6] = fma2(wd.x, fb, acc2[6]); acc2[7] = fma2(wd.y, fb, acc2[7]);
            }
        }
    }

    // ---------------- Epilogue: stage via smem, coalesced store ----------------------
    __syncthreads();
    float* stage = wk_s;     // reuse
    {
        const int qr = lid >> 2;
        const int qc = 2 * (lid & 3);
        #pragma unroll
        for (int t = 0; t < 2; t++) {
            const int mr = wm * 32 + t * 16 + qr;
            #pragma unroll
            for (int nt = 0; nt < 4; nt++) {
                const int oc = wn * 32 + nt * 8 + qc;
                *(float2*)&stage[mr * STAGE_STRIDE + oc] =
                    make_float2(accf[t][nt][0], accf[t][nt][1]);
                *(float2*)&stage[(mr + 8) * STAGE_STRIDE + oc] =
                    make_float2(accf[t][nt][2], accf[t][nt][3]);
            }
        }
    }
    __syncthreads();
    {
        #pragma unroll
        for (int ow = 0; ow < 16; ow++) {
            const int o = wid * 16 + ow;
            const float bias = lin_b[o];
            float* orow = &out[(b * COUT + o) * N_ + n0];
            #pragma unroll
            for (int i = 0; i < 2; i++) {
                const int mm = lid + 32 * i;
                orow[mm] = leaky(stage[mm * STAGE_STRIDE + o] + bias);
            }
        }
    }
}

// ---------------------------------------------------------------------------
extern "C" void kernel_launch(void* const* d_in, const int* in_sizes, int n_in,
                              void* d_out, int out_size)
{
    const float* xyz  = (const float*)d_in[0];
    const float* feat = (const float*)d_in[1];
    const int*   knn  = (const int*)d_in[2];
    const float* w1   = (const float*)d_in[3];
    const float* b1   = (const float*)d_in[4];
    const float* w2   = (const float*)d_in[5];
    const float* b2   = (const float*)d_in[6];
    const float* lw   = (const float*)d_in[7];
    const float* lb   = (const float*)d_in[8];
    float* out = (float*)d_out;

    cudaFuncSetAttribute(pointconv_main, cudaFuncAttributeMaxDynamicSharedMemorySize, SMEM_TOTAL);

    pack_wfrag<<<(NCHUNK * 4096 + 255) / 256, 256>>>(lw);

    dim3 gp((N_ + 255) / 256, B_ * CP);
    pack_feats<<<gp, 256>>>(xyz, feat);

    pointconv_main<<<(B_ * N_) / MT, 256, SMEM_TOTAL>>>(xyz, knn, w1, b1, w2, b2, lb, out);
}

// round 16
// speedup vs baseline: 2.4245x; 1.1319x over previous
#include <cuda_runtime.h>
#include <cuda_fp16.h>

typedef unsigned int       u32;
typedef unsigned long long u64;

// Problem constants
#define B_     4
#define N_     16384
#define KNN    16
#define CIN    64
#define COUT   128
#define MT     32             // points per block
#define NCHUNK 9              // chunks of 128 j (j = c*16 + w, c padded to 72)
#define NEG_SLOPE 0.1f

// smem byte offsets
#define A0_OFF     0                      // A tile buf0: 2 subtiles (32x64 fp16 = 4096B each)
#define A1_OFF     8192
#define WK16_OFF   16384                  // wk fp16 [32 pts][16 w][16 k] : 512B/pt = 16384B
#define F16_OFF    32768                  // F16 [32 pts][16 k][72 c] fp16 : 2304B/pt = 73728B
#define F16_MS     2304
#define GID_OFF    (F16_OFF + 73728)      // 106496: int[512] byte-offsets
#define SMEM_TOTAL (GID_OFF + 2048)       // 108544 -> 2 CTAs/SM
#define STAGE_OFF  F16_OFF                // epilogue stage reuses F16 region
#define STAGE_STRIDE 136

// Static device scratch
__device__ __align__(16) __half g_feats16[B_ * N_ * 72];         // padded channel-last rows
// W fragments: [q(9)][wn(8)][ks(8)][lane(32)][4 u32] fp16x2
__device__ __align__(16) u32    g_wf[9 * 8 * 8 * 32 * 4];

__device__ __forceinline__ float leaky(float x) { return x >= 0.f ? x : NEG_SLOPE * x; }

// ---- helpers ----------------------------------------------------------------
__device__ __forceinline__ u32 s2u(const void* p) {
    u32 a;
    asm("{ .reg .u64 t; cvta.to.shared.u64 t, %1; cvt.u32.u64 %0, t; }" : "=r"(a) : "l"(p));
    return a;
}
__device__ __forceinline__ u32 sw128(u32 off) { return off ^ ((off >> 3) & 0x70); }

__device__ __forceinline__ void sts16f(u32 addr, float v) {
    asm volatile("{ .reg .b16 h; cvt.rn.f16.f32 h, %1; st.shared.b16 [%0], h; }"
                 :: "r"(addr), "f"(v) : "memory");
}
__device__ __forceinline__ void ldsm4(u32* r, u32 addr) {
    asm volatile("ldmatrix.sync.aligned.m8n8.x4.shared.b16 {%0,%1,%2,%3}, [%4];"
                 : "=r"(r[0]), "=r"(r[1]), "=r"(r[2]), "=r"(r[3]) : "r"(addr));
}
__device__ __forceinline__ void ldsm2t(u32& b0, u32& b1, u32 addr) {
    asm volatile("ldmatrix.sync.aligned.m8n8.x2.trans.shared.b16 {%0,%1}, [%2];"
                 : "=r"(b0), "=r"(b1) : "r"(addr));
}
__device__ __forceinline__ void mma_f16(float* c, const u32* a, u32 b0, u32 b1) {
    asm volatile("mma.sync.aligned.m16n8k16.row.col.f32.f16.f16.f32 "
                 "{%0,%1,%2,%3}, {%4,%5,%6,%7}, {%8,%9}, {%0,%1,%2,%3};"
                 : "+f"(c[0]), "+f"(c[1]), "+f"(c[2]), "+f"(c[3])
                 : "r"(a[0]), "r"(a[1]), "r"(a[2]), "r"(a[3]), "r"(b0), "r"(b1));
}
__device__ __forceinline__ void mma_f16_z(float& d0, float& d1, float& d2, float& d3,
                                          const u32* a, u32 b0, u32 b1) {
    asm volatile("mma.sync.aligned.m16n8k16.row.col.f32.f16.f16.f32 "
                 "{%0,%1,%2,%3}, {%4,%5,%6,%7}, {%8,%9}, {%10,%11,%12,%13};"
                 : "=f"(d0), "=f"(d1), "=f"(d2), "=f"(d3)
                 : "r"(a[0]), "r"(a[1]), "r"(a[2]), "r"(a[3]), "r"(b0), "r"(b1),
                   "f"(0.f), "f"(0.f), "f"(0.f), "f"(0.f));
}

// ---------------------------------------------------------------------------
// pack_wfrag: lin_w -> mma B-fragment layout (fp16), j = c*16 + w, c padded to 72.
// g_wf[q][wn][ks][lane][r]; uint4 per lane per ks = (n0 klo, n0 khi, n1 klo, n1 khi)
// ---------------------------------------------------------------------------
__global__ void pack_wfrag(const float* __restrict__ lin_w) {
    int idx = blockIdx.x * blockDim.x + threadIdx.x;
    if (idx >= 9 * 8 * 8 * 32 * 4) return;
    const int r    = idx & 3;
    const int lane = (idx >> 2) & 31;
    const int ks   = (idx >> 7) & 7;
    const int wn   = (idx >> 10) & 7;
    const int q    = idx >> 13;

    const int o = wn * 16 + (r >> 1) * 8 + (lane >> 2);
    float v[2];
    #pragma unroll
    for (int i = 0; i < 2; i++) {
        const int k16 = 2 * (lane & 3) + (r & 1) * 8 + i;
        const int j   = q * 128 + ks * 16 + k16;
        const int w   = j & 15;
        const int c   = j >> 4;
        float x = 0.f;
        if (c < 64)      x = lin_w[o * 1072 + w * 67 + (c + 3)];
        else if (c < 67) x = lin_w[o * 1072 + w * 67 + (c - 64)];
        v[i] = x;
    }
    __half2 h = __floats2half2_rn(v[0], v[1]);
    g_wf[idx] = *(u32*)&h;
}

// ---------------------------------------------------------------------------
// pack_feats16: fp16 channel-last padded rows g_feats16[(b*N+n)*72 + c]
// c: 0..63 features, 64..66 xyz, 67..71 zero. One uint4 (8 halfs) per thread.
// ---------------------------------------------------------------------------
__global__ void pack_feats16(const float* __restrict__ xyz, const float* __restrict__ feat) {
    int n = blockIdx.x * blockDim.x + threadIdx.x;
    int bg = blockIdx.y;                   // b*9 + cg
    int b = bg / 9;
    int cg = bg % 9;
    if (n >= N_) return;
    __half2 h[4];
    if (cg < 8) {
        #pragma unroll
        for (int i = 0; i < 4; i++) {
            float f0 = feat[(b * CIN + cg * 8 + 2 * i) * N_ + n];
            float f1 = feat[(b * CIN + cg * 8 + 2 * i + 1) * N_ + n];
            h[i] = __floats2half2_rn(f0, f1);
        }
    } else {
        float x0 = xyz[(b * 3 + 0) * N_ + n];
        float x1 = xyz[(b * 3 + 1) * N_ + n];
        float x2 = xyz[(b * 3 + 2) * N_ + n];
        h[0] = __floats2half2_rn(x0, x1);
        h[1] = __floats2half2_rn(x2, 0.f);
        h[2] = __floats2half2_rn(0.f, 0.f);
        h[3] = h[2];
    }
    uint4 v = make_uint4(*(u32*)&h[0], *(u32*)&h[1], *(u32*)&h[2], *(u32*)&h[3]);
    *(uint4*)&g_feats16[(u64)(b * N_ + n) * 72 + cg * 8] = v;
}

// ---------------------------------------------------------------------------
// Main kernel: 32 points/block, 256 threads, 2 CTAs/SM.
// Phase 2 done via one m16n8k16 mma per point per chunk.
// ---------------------------------------------------------------------------
extern __shared__ char s_raw[];

__global__ __launch_bounds__(256, 2)
void pointconv_main(const float* __restrict__ xyz, const int* __restrict__ knn,
                    const float* __restrict__ w1, const float* __restrict__ b1,
                    const float* __restrict__ w2, const float* __restrict__ b2,
                    const float* __restrict__ lin_b, float* __restrict__ out)
{
    const u32 sbase = s2u(s_raw);
    int* gid_s = (int*)(s_raw + GID_OFF);

    const int tid = threadIdx.x;
    const int wid = tid >> 5;
    const int lid = tid & 31;
    const int p0  = blockIdx.x * MT;
    const int b   = p0 / N_;
    const int n0  = p0 % N_;

    // ---------------- Phase 1: weight MLP -> wk16 smem [m][w][k] fp16 ---------------
    {
        const int m  = tid >> 3;               // 0..31
        const int kh = (tid & 7) * 2;
        const int n  = n0 + m;
        const float cx0 = xyz[(b * 3 + 0) * N_ + n];
        const float cx1 = xyz[(b * 3 + 1) * N_ + n];
        const float cx2 = xyz[(b * 3 + 2) * N_ + n];
        #pragma unroll
        for (int kk = 0; kk < 2; kk++) {
            const int k = kh + kk;
            const int idx = knn[(b * N_ + n) * KNN + k];
            gid_s[m * KNN + k] = (b * N_ + idx) * 144;      // byte offset into g_feats16
            const float d0 = xyz[(b * 3 + 0) * N_ + idx] - cx0;
            const float d1 = xyz[(b * 3 + 1) * N_ + idx] - cx1;
            const float d2 = xyz[(b * 3 + 2) * N_ + idx] - cx2;
            float h[8];
            #pragma unroll
            for (int o = 0; o < 8; o++) {
                float s = fmaf(w1[o * 3 + 0], d0,
                          fmaf(w1[o * 3 + 1], d1,
                          fmaf(w1[o * 3 + 2], d2, b1[o])));
                h[o] = leaky(s);
            }
            const u32 wkaddr = sbase + WK16_OFF + (u32)(m * 512 + k * 2);
            #pragma unroll
            for (int o = 0; o < 16; o++) {
                float s = b2[o];
                #pragma unroll
                for (int hh = 0; hh < 8; hh++) s = fmaf(w2[o * 8 + hh], h[hh], s);
                sts16f(wkaddr + o * 32, leaky(s));          // [m][w=o][k]
            }
        }
    }
    __syncthreads();

    // ---------------- Gather: neighbor rows -> F16[m][k][72] (once) ------------------
    {
        #pragma unroll
        for (int r = tid; r < MT * KNN; r += 256) {
            const char* src = (const char*)g_feats16 + gid_s[r];
            uint4* dst = (uint4*)(s_raw + F16_OFF + (r >> 4) * F16_MS + (r & 15) * 144);
            #pragma unroll
            for (int i = 0; i < 9; i++) dst[i] = ((const uint4*)src)[i];
        }
    }
    __syncthreads();

    // per-warp roles
    const int pbase = wid * 4;                 // phase-2: 4 points per warp
    // main GEMM: all warps share m (32 rows), each owns 16 n-cols (wn = wid)

    float accf[2][2][4];                       // [mtile][ntile][frag]
    #pragma unroll
    for (int t = 0; t < 2; t++)
        #pragma unroll
        for (int nt = 0; nt < 2; nt++)
            #pragma unroll
            for (int r = 0; r < 4; r++) accf[t][nt][r] = 0.f;

    const u32 a_row = (u32)((lid & 7) + ((lid >> 3) & 1) * 8);
    const u32 a_kb  = (u32)(((lid >> 4) & 1) * 16);
    const int jl    = 32 * (lid & 3) + (lid >> 2);   // phase-2 output j-local base
    const u32 wk_la = sbase + WK16_OFF + (u32)((lid & 15) * 32 + (lid >> 4) * 16);
    const u32 f_la  = sbase + F16_OFF + (u32)((lid & 15) * 144);

    // ---------------- Chunk loop (one barrier per chunk) -----------------------------
    for (int q = 0; q < NCHUNK; q++) {
        const u32 abuf = sbase + ((q & 1) ? (u32)A1_OFF : (u32)A0_OFF);

        // ---- phase 2: one mma per point, output -> A tile ----
        #pragma unroll
        for (int pp = 0; pp < 4; pp++) {
            const int p = pbase + pp;
            u32 af[4];
            ldsm4(af, wk_la + (u32)(p * 512));
            u32 b0, b1;
            ldsm2t(b0, b1, f_la + (u32)(p * F16_MS + q * 16));
            float d0, d1, d2, d3;
            mma_f16_z(d0, d1, d2, d3, af, b0, b1);
            const u32 base = abuf + (u32)((jl >> 6) * 4096);
            const u32 prow = (u32)(p * 128);
            sts16f(base + sw128(prow + (u32)((jl      & 63) * 2)), d0);
            sts16f(base + sw128(prow + (u32)(((jl + 16) & 63) * 2)), d1);
            sts16f(base + sw128(prow + (u32)(((jl + 8)  & 63) * 2)), d2);
            sts16f(base + sw128(prow + (u32)(((jl + 24) & 63) * 2)), d3);
        }
        __syncthreads();

        // ---- main GEMM: A from smem (ldsm), B fragments from gmem/L2 ----
        {
            const uint4* wf = (const uint4*)g_wf + (u64)((q * 8 + wid) * 8) * 32;
            #pragma unroll
            for (int ks = 0; ks < 8; ks++) {
                const uint4 bv = wf[ks * 32 + lid];
                u32 ah[2][4];
                #pragma unroll
                for (int t = 0; t < 2; t++) {
                    const u32 addr = abuf + (u32)((ks >> 2) * 4096)
                                   + sw128((u32)((t * 16) * 128) + a_row * 128
                                           + (u32)((ks & 3) * 32) + a_kb);
                    ldsm4(ah[t], addr);
                }
                #pragma unroll
                for (int t = 0; t < 2; t++) {
                    mma_f16(accf[t][0], ah[t], bv.x, bv.y);
                    mma_f16(accf[t][1], ah[t], bv.z, bv.w);
                }
            }
        }
    }

    // ---------------- Epilogue: stage via smem, coalesced store ----------------------
    __syncthreads();
    float* stage = (float*)(s_raw + STAGE_OFF);
    {
        const int qr = lid >> 2;
        const int qc = 2 * (lid & 3);
        #pragma unroll
        for (int t = 0; t < 2; t++) {
            const int mr = t * 16 + qr;
            #pragma unroll
            for (int nt = 0; nt < 2; nt++) {
                const int oc = wid * 16 + nt * 8 + qc;
                *(float2*)&stage[mr * STAGE_STRIDE + oc] =
                    make_float2(accf[t][nt][0], accf[t][nt][1]);
                *(float2*)&stage[(mr + 8) * STAGE_STRIDE + oc] =
                    make_float2(accf[t][nt][2], accf[t][nt][3]);
            }
        }
    }
    __syncthreads();
    {
        const int o  = tid >> 1;               // 0..127
        const int mh = (tid & 1) * 16;
        const float bias = lin_b[o];
        float* orow = &out[(b * COUT + o) * N_ + n0 + mh];
        #pragma unroll
        for (int i = 0; i < 4; i++) {
            float4 v;
            v.x = leaky(stage[(mh + 4 * i + 0) * STAGE_STRIDE + o] + bias);
            v.y = leaky(stage[(mh + 4 * i + 1) * STAGE_STRIDE + o] + bias);
            v.z = leaky(stage[(mh + 4 * i + 2) * STAGE_STRIDE + o] + bias);
            v.w = leaky(stage[(mh + 4 * i + 3) * STAGE_STRIDE + o] + bias);
            *(float4*)(orow + 4 * i) = v;
        }
    }
}

// ---------------------------------------------------------------------------
extern "C" void kernel_launch(void* const* d_in, const int* in_sizes, int n_in,
                              void* d_out, int out_size)
{
    const float* xyz  = (const float*)d_in[0];
    const float* feat = (const float*)d_in[1];
    const int*   knn  = (const int*)d_in[2];
    const float* w1   = (const float*)d_in[3];
    const float* b1   = (const float*)d_in[4];
    const float* w2   = (const float*)d_in[5];
    const float* b2   = (const float*)d_in[6];
    const float* lw   = (const float*)d_in[7];
    const float* lb   = (const float*)d_in[8];
    float* out = (float*)d_out;

    cudaFuncSetAttribute(pointconv_main, cudaFuncAttributeMaxDynamicSharedMemorySize, SMEM_TOTAL);

    pack_wfrag<<<(9 * 8 * 8 * 32 * 4 + 255) / 256, 256>>>(lw);

    dim3 gp((N_ + 255) / 256, B_ * 9);
    pack_feats16<<<gp, 256>>>(xyz, feat);

    pointconv_main<<<(B_ * N_) / MT, 256, SMEM_TOTAL>>>(xyz, knn, w1, b1, w2, b2, lb, out);
}

// round 17
// speedup vs baseline: 2.7112x; 1.1183x over previous
#include <cuda_runtime.h>
#include <cuda_fp16.h>

typedef unsigned int       u32;
typedef unsigned long long u64;

// Problem constants
#define B_     4
#define N_     16384
#define KNN    16
#define CIN    64
#define COUT   128
#define MT     32             // points per block
#define NCHUNK 9              // chunks of 128 j (j = c*16 + w, c padded to 72)
#define NEG_SLOPE 0.1f

// smem byte offsets
#define A0_OFF     0                      // A tile buf0: 2 subtiles (32x64 fp16 = 4096B each)
#define A1_OFF     8192
#define WK16_OFF   16384                  // wk fp16 [32 pts][16 w][16 k] : 512B/pt = 16384B
#define F16_OFF    32768                  // F16 [32 pts][16 k][72 c] fp16 : 2304B/pt = 73728B
#define F16_MS     2304
#define SMEM_TOTAL (F16_OFF + 73728)      // 106496 -> 2 CTAs/SM
#define STAGE_OFF  F16_OFF                // epilogue stage reuses F16 region
#define STAGE_STRIDE 136

// Static device scratch
__device__ __align__(16) __half g_feats16[B_ * N_ * 72];         // padded channel-last rows
// W fragments: [q(9)][wn(8)][ks(8)][lane(32)][4 u32] fp16x2
__device__ __align__(16) u32    g_wf[9 * 8 * 8 * 32 * 4];

__device__ __forceinline__ float leaky(float x) { return x >= 0.f ? x : NEG_SLOPE * x; }

// ---- helpers ----------------------------------------------------------------
__device__ __forceinline__ u32 s2u(const void* p) {
    u32 a;
    asm("{ .reg .u64 t; cvta.to.shared.u64 t, %1; cvt.u32.u64 %0, t; }" : "=r"(a) : "l"(p));
    return a;
}
__device__ __forceinline__ u32 sw128(u32 off) { return off ^ ((off >> 3) & 0x70); }

__device__ __forceinline__ u32 f16x2pack(float lo, float hi) {
    u32 r;
    asm("cvt.rn.f16x2.f32 %0, %1, %2;" : "=r"(r) : "f"(hi), "f"(lo));
    return r;
}
__device__ __forceinline__ void sts16f(u32 addr, float v) {
    asm volatile("{ .reg .b16 h; cvt.rn.f16.f32 h, %1; st.shared.b16 [%0], h; }"
                 :: "r"(addr), "f"(v) : "memory");
}
__device__ __forceinline__ void sts32(u32 addr, u32 v) {
    asm volatile("st.shared.b32 [%0], %1;" :: "r"(addr), "r"(v) : "memory");
}
__device__ __forceinline__ void ldsm4(u32* r, u32 addr) {
    asm volatile("ldmatrix.sync.aligned.m8n8.x4.shared.b16 {%0,%1,%2,%3}, [%4];"
                 : "=r"(r[0]), "=r"(r[1]), "=r"(r[2]), "=r"(r[3]) : "r"(addr));
}
__device__ __forceinline__ void ldsm2t(u32& b0, u32& b1, u32 addr) {
    asm volatile("ldmatrix.sync.aligned.m8n8.x2.trans.shared.b16 {%0,%1}, [%2];"
                 : "=r"(b0), "=r"(b1) : "r"(addr));
}
__device__ __forceinline__ void mma_f16(float* c, const u32* a, u32 b0, u32 b1) {
    asm volatile("mma.sync.aligned.m16n8k16.row.col.f32.f16.f16.f32 "
                 "{%0,%1,%2,%3}, {%4,%5,%6,%7}, {%8,%9}, {%0,%1,%2,%3};"
                 : "+f"(c[0]), "+f"(c[1]), "+f"(c[2]), "+f"(c[3])
                 : "r"(a[0]), "r"(a[1]), "r"(a[2]), "r"(a[3]), "r"(b0), "r"(b1));
}
__device__ __forceinline__ void mma_f16_z(float& d0, float& d1, float& d2, float& d3,
                                          const u32* a, u32 b0, u32 b1) {
    asm volatile("mma.sync.aligned.m16n8k16.row.col.f32.f16.f16.f32 "
                 "{%0,%1,%2,%3}, {%4,%5,%6,%7}, {%8,%9}, {%10,%11,%12,%13};"
                 : "=f"(d0), "=f"(d1), "=f"(d2), "=f"(d3)
                 : "r"(a[0]), "r"(a[1]), "r"(a[2]), "r"(a[3]), "r"(b0), "r"(b1),
                   "f"(0.f), "f"(0.f), "f"(0.f), "f"(0.f));
}

// ---------------------------------------------------------------------------
// pack_wfrag: lin_w -> mma B-fragment layout (fp16), j = c*16 + w, c padded to 72.
// ---------------------------------------------------------------------------
__global__ void pack_wfrag(const float* __restrict__ lin_w) {
    int idx = blockIdx.x * blockDim.x + threadIdx.x;
    if (idx >= 9 * 8 * 8 * 32 * 4) return;
    const int r    = idx & 3;
    const int lane = (idx >> 2) & 31;
    const int ks   = (idx >> 7) & 7;
    const int wn   = (idx >> 10) & 7;
    const int q    = idx >> 13;

    const int o = wn * 16 + (r >> 1) * 8 + (lane >> 2);
    float v[2];
    #pragma unroll
    for (int i = 0; i < 2; i++) {
        const int k16 = 2 * (lane & 3) + (r & 1) * 8 + i;
        const int j   = q * 128 + ks * 16 + k16;
        const int w   = j & 15;
        const int c   = j >> 4;
        float x = 0.f;
        if (c < 64)      x = lin_w[o * 1072 + w * 67 + (c + 3)];
        else if (c < 67) x = lin_w[o * 1072 + w * 67 + (c - 64)];
        v[i] = x;
    }
    __half2 h = __floats2half2_rn(v[0], v[1]);
    g_wf[idx] = *(u32*)&h;
}

// ---------------------------------------------------------------------------
// pack_feats16: fp16 channel-last padded rows g_feats16[(b*N+n)*72 + c]
// ---------------------------------------------------------------------------
__global__ void pack_feats16(const float* __restrict__ xyz, const float* __restrict__ feat) {
    int n = blockIdx.x * blockDim.x + threadIdx.x;
    int bg = blockIdx.y;                   // b*9 + cg
    int b = bg / 9;
    int cg = bg % 9;
    if (n >= N_) return;
    __half2 h[4];
    if (cg < 8) {
        #pragma unroll
        for (int i = 0; i < 4; i++) {
            float f0 = feat[(b * CIN + cg * 8 + 2 * i) * N_ + n];
            float f1 = feat[(b * CIN + cg * 8 + 2 * i + 1) * N_ + n];
            h[i] = __floats2half2_rn(f0, f1);
        }
    } else {
        float x0 = xyz[(b * 3 + 0) * N_ + n];
        float x1 = xyz[(b * 3 + 1) * N_ + n];
        float x2 = xyz[(b * 3 + 2) * N_ + n];
        h[0] = __floats2half2_rn(x0, x1);
        h[1] = __floats2half2_rn(x2, 0.f);
        h[2] = __floats2half2_rn(0.f, 0.f);
        h[3] = h[2];
    }
    uint4 v = make_uint4(*(u32*)&h[0], *(u32*)&h[1], *(u32*)&h[2], *(u32*)&h[3]);
    *(uint4*)&g_feats16[(u64)(b * N_ + n) * 72 + cg * 8] = v;
}

// ---------------------------------------------------------------------------
// Main kernel: 32 points/block, 256 threads, 2 CTAs/SM.
// ---------------------------------------------------------------------------
extern __shared__ char s_raw[];

__global__ __launch_bounds__(256, 2)
void pointconv_main(const float* __restrict__ xyz, const int* __restrict__ knn,
                    const float* __restrict__ w1, const float* __restrict__ b1,
                    const float* __restrict__ w2, const float* __restrict__ b2,
                    const float* __restrict__ lin_b, float* __restrict__ out)
{
    const u32 sbase = s2u(s_raw);

    const int tid = threadIdx.x;
    const int wid = tid >> 5;
    const int lid = tid & 31;
    const int p0  = blockIdx.x * MT;
    const int b   = p0 / N_;
    const int n0  = p0 % N_;

    // ---------------- Phase 1: weight MLP -> wk16 smem [m][w][k] fp16 ---------------
    {
        const int m  = tid >> 3;               // 0..31
        const int kh = (tid & 7) * 2;
        const int n  = n0 + m;
        const float cx0 = xyz[(b * 3 + 0) * N_ + n];
        const float cx1 = xyz[(b * 3 + 1) * N_ + n];
        const float cx2 = xyz[(b * 3 + 2) * N_ + n];
        #pragma unroll
        for (int kk = 0; kk < 2; kk++) {
            const int k = kh + kk;
            const int idx = knn[(b * N_ + n) * KNN + k];
            const float d0 = xyz[(b * 3 + 0) * N_ + idx] - cx0;
            const float d1 = xyz[(b * 3 + 1) * N_ + idx] - cx1;
            const float d2 = xyz[(b * 3 + 2) * N_ + idx] - cx2;
            float h[8];
            #pragma unroll
            for (int o = 0; o < 8; o++) {
                float s = fmaf(w1[o * 3 + 0], d0,
                          fmaf(w1[o * 3 + 1], d1,
                          fmaf(w1[o * 3 + 2], d2, b1[o])));
                h[o] = leaky(s);
            }
            const u32 wkaddr = sbase + WK16_OFF + (u32)(m * 512 + k * 2);
            #pragma unroll
            for (int o = 0; o < 16; o++) {
                float s = b2[o];
                #pragma unroll
                for (int hh = 0; hh < 8; hh++) s = fmaf(w2[o * 8 + hh], h[hh], s);
                sts16f(wkaddr + o * 32, leaky(s));          // [m][w=o][k]
            }
        }
    }

    // ---------------- Gather (coalesced): neighbor rows -> F16[m][k][72] -------------
    // work item t -> (row = t/9, i = t%9); 9 consecutive uint4 per row.
    {
        #pragma unroll
        for (int t = tid; t < MT * KNN * 9; t += 256) {
            const int row = (int)(((u32)t * 0x1C72u) >> 16);   // t/9 for t < 4608
            const int i   = t - row * 9;
            const int m   = row >> 4;
            const int k   = row & 15;
            const int idx = knn[(b * N_ + n0 + m) * KNN + k];
            const uint4 v = *((const uint4*)(g_feats16 + (u64)(b * N_ + idx) * 72) + i);
            *(uint4*)(s_raw + F16_OFF + row * 144 + i * 16) = v;
        }
    }
    __syncthreads();

    // per-warp roles
    const int pbase = wid * 4;                 // phase-2: 4 points per warp

    float accf[2][2][4];
    #pragma unroll
    for (int t = 0; t < 2; t++)
        #pragma unroll
        for (int nt = 0; nt < 2; nt++)
            #pragma unroll
            for (int r = 0; r < 4; r++) accf[t][nt][r] = 0.f;

    const u32 a_row = (u32)((lid & 7) + ((lid >> 3) & 1) * 8);
    const u32 a_kb  = (u32)(((lid >> 4) & 1) * 16);
    const int jl    = 32 * (lid & 3) + (lid >> 2);   // phase-2 output j-local base
    const u32 wk_la = sbase + WK16_OFF + (u32)((lid & 15) * 32 + (lid >> 4) * 16);
    const u32 f_la  = sbase + F16_OFF + (u32)((lid & 15) * 144);
    const bool st_act = (((lid >> 2) & 1) == 0);     // even-w lanes store pairs

    // ---------------- Chunk loop (one barrier per chunk) -----------------------------
    for (int q = 0; q < NCHUNK; q++) {
        const u32 abuf = sbase + ((q & 1) ? (u32)A1_OFF : (u32)A0_OFF);

        // ---- B prefetch for this chunk (latency hides under phase-2 + barrier) ----
        uint4 bv[8];
        {
            const uint4* wf = (const uint4*)g_wf + (u64)((q * 8 + wid) * 8) * 32;
            #pragma unroll
            for (int ks = 0; ks < 8; ks++) bv[ks] = wf[ks * 32 + lid];
        }

        // ---- phase 2: one mma per point; pair halves via shfl, STS.32 ----
        #pragma unroll
        for (int pp = 0; pp < 4; pp++) {
            const int p = pbase + pp;
            u32 af[4];
            ldsm4(af, wk_la + (u32)(p * 512));
            u32 b0, b1;
            ldsm2t(b0, b1, f_la + (u32)(p * F16_MS + q * 16));
            float d0, d1, d2, d3;
            mma_f16_z(d0, d1, d2, d3, af, b0, b1);
            const float e0 = __shfl_down_sync(0xffffffffu, d0, 4);
            const float e1 = __shfl_down_sync(0xffffffffu, d1, 4);
            const float e2 = __shfl_down_sync(0xffffffffu, d2, 4);
            const float e3 = __shfl_down_sync(0xffffffffu, d3, 4);
            if (st_act) {
                const u32 base = abuf + (u32)((jl >> 6) * 4096);
                const u32 prow = (u32)(p * 128);
                sts32(base + sw128(prow + (u32)(((jl)      & 63) * 2)), f16x2pack(d0, e0));
                sts32(base + sw128(prow + (u32)(((jl + 16) & 63) * 2)), f16x2pack(d1, e1));
                sts32(base + sw128(prow + (u32)(((jl + 8)  & 63) * 2)), f16x2pack(d2, e2));
                sts32(base + sw128(prow + (u32)(((jl + 24) & 63) * 2)), f16x2pack(d3, e3));
            }
        }
        __syncthreads();

        // ---- main GEMM: A from smem (ldsm), B from prefetched regs ----
        #pragma unroll
        for (int ks = 0; ks < 8; ks++) {
            u32 ah[2][4];
            #pragma unroll
            for (int t = 0; t < 2; t++) {
                const u32 addr = abuf + (u32)((ks >> 2) * 4096)
                               + sw128((u32)((t * 16) * 128) + a_row * 128
                                       + (u32)((ks & 3) * 32) + a_kb);
                ldsm4(ah[t], addr);
            }
            #pragma unroll
            for (int t = 0; t < 2; t++) {
                mma_f16(accf[t][0], ah[t], bv[ks].x, bv[ks].y);
                mma_f16(accf[t][1], ah[t], bv[ks].z, bv[ks].w);
            }
        }
    }

    // ---------------- Epilogue: stage via smem, coalesced store ----------------------
    // (F16 region is dead: all phase-2 reads preceded the last chunk barrier)
    float* stage = (float*)(s_raw + STAGE_OFF);
    {
        const int qr = lid >> 2;
        const int qc = 2 * (lid & 3);
        #pragma unroll
        for (int t = 0; t < 2; t++) {
            const int mr = t * 16 + qr;
            #pragma unroll
            for (int nt = 0; nt < 2; nt++) {
                const int oc = wid * 16 + nt * 8 + qc;
                *(float2*)&stage[mr * STAGE_STRIDE + oc] =
                    make_float2(accf[t][nt][0], accf[t][nt][1]);
                *(float2*)&stage[(mr + 8) * STAGE_STRIDE + oc] =
                    make_float2(accf[t][nt][2], accf[t][nt][3]);
            }
        }
    }
    __syncthreads();
    {
        const int o  = tid >> 1;               // 0..127
        const int mh = (tid & 1) * 16;
        const float bias = lin_b[o];
        float* orow = &out[(b * COUT + o) * N_ + n0 + mh];
        #pragma unroll
        for (int i = 0; i < 4; i++) {
            float4 v;
            v.x = leaky(stage[(mh + 4 * i + 0) * STAGE_STRIDE + o] + bias);
            v.y = leaky(stage[(mh + 4 * i + 1) * STAGE_STRIDE + o] + bias);
            v.z = leaky(stage[(mh + 4 * i + 2) * STAGE_STRIDE + o] + bias);
            v.w = leaky(stage[(mh + 4 * i + 3) * STAGE_STRIDE + o] + bias);
            *(float4*)(orow + 4 * i) = v;
        }
    }
}

// ---------------------------------------------------------------------------
extern "C" void kernel_launch(void* const* d_in, const int* in_sizes, int n_in,
                              void* d_out, int out_size)
{
    const float* xyz  = (const float*)d_in[0];
    const float* feat = (const float*)d_in[1];
    const int*   knn  = (const int*)d_in[2];
    const float* w1   = (const float*)d_in[3];
    const float* b1   = (const float*)d_in[4];
    const float* w2   = (const float*)d_in[5];
    const float* b2   = (const float*)d_in[6];
    const float* lw   = (const float*)d_in[7];
    const float* lb   = (const float*)d_in[8];
    float* out = (float*)d_out;

    cudaFuncSetAttribute(pointconv_main, cudaFuncAttributeMaxDynamicSharedMemorySize, SMEM_TOTAL);

    pack_wfrag<<<(9 * 8 * 8 * 32 * 4 + 255) / 256, 256>>>(lw);

    dim3 gp((N_ + 255) / 256, B_ * 9);
    pack_feats16<<<gp, 256>>>(xyz, feat);

    pointconv_main<<<(B_ * N_) / MT, 256, SMEM_TOTAL>>>(xyz, knn, w1, b1, w2, b2, lb, out);
}